// round 2
// baseline (speedup 1.0000x reference)
#include <cuda_runtime.h>
#include <math.h>

#define SEQ 128
#define BATCH 128
#define DIM 1024

// Scratch for the precomputed input projection xp = x @ Wx + b  : [SEQ, BATCH, DIM]
__device__ float g_xp[(size_t)SEQ * BATCH * DIM];

// ---------------------------------------------------------------------------
// Kernel 1: xp[M=16384, N=1024] = X[16384,1024] @ Wx[1024,1024] + b
// Tiles: BM=64, BN=64, BK=16; 256 threads; 4x4 register microtile.
// ---------------------------------------------------------------------------
__global__ __launch_bounds__(256) void gemm_xp_kernel(
    const float* __restrict__ X,
    const float* __restrict__ W,
    const float* __restrict__ bias)
{
    const int BM = 64, BN = 64, BK = 16;
    __shared__ float As[BK][BM];   // transposed: As[k][m]
    __shared__ float Bs[BK][BN];   // Bs[k][n]

    const int bx = blockIdx.x;     // N tile index (0..15)
    const int by = blockIdx.y;     // M tile index (0..255)
    const int tid = threadIdx.x;
    const int tr = tid >> 4;       // 0..15 row group
    const int tc = tid & 15;       // 0..15 col group
    const int row0 = by * BM;
    const int col0 = bx * BN;

    float acc[4][4] = {};

    for (int k0 = 0; k0 < DIM; k0 += BK) {
        // Load A tile: 64 rows x 16 k, one float4 per thread, store transposed.
        {
            const int m  = tid >> 2;          // 0..63
            const int kq = (tid & 3) << 2;    // 0,4,8,12
            float4 v = *reinterpret_cast<const float4*>(
                &X[(size_t)(row0 + m) * DIM + k0 + kq]);
            As[kq + 0][m] = v.x;
            As[kq + 1][m] = v.y;
            As[kq + 2][m] = v.z;
            As[kq + 3][m] = v.w;
        }
        // Load B tile: 16 k x 64 n, one float4 per thread.
        {
            const int kr = tid >> 4;          // 0..15
            const int nq = (tid & 15) << 2;   // 0..60
            float4 v = *reinterpret_cast<const float4*>(
                &W[(size_t)(k0 + kr) * DIM + col0 + nq]);
            *reinterpret_cast<float4*>(&Bs[kr][nq]) = v;
        }
        __syncthreads();

        #pragma unroll
        for (int k = 0; k < BK; k++) {
            float4 a  = *reinterpret_cast<const float4*>(&As[k][tr << 2]);
            float4 bv = *reinterpret_cast<const float4*>(&Bs[k][tc << 2]);
            float av[4] = {a.x, a.y, a.z, a.w};
            float bb[4] = {bv.x, bv.y, bv.z, bv.w};
            #pragma unroll
            for (int i = 0; i < 4; i++)
                #pragma unroll
                for (int j = 0; j < 4; j++)
                    acc[i][j] += av[i] * bb[j];
        }
        __syncthreads();
    }

    #pragma unroll
    for (int i = 0; i < 4; i++) {
        const int r = row0 + (tr << 2) + i;
        #pragma unroll
        for (int j = 0; j < 4; j++) {
            const int c = col0 + (tc << 2) + j;
            g_xp[(size_t)r * DIM + c] = acc[i][j] + bias[c];
        }
    }
}

// ---------------------------------------------------------------------------
// Kernel 2: one recurrence step
//   out[B=128, D=1024] = tanh( xp[t] + H[128,1024] @ Wh[1024,1024] )
// Tiles: BM=32, BN=32, BK=32; 256 threads; 2x2 microtile. Grid = 32 x 4 = 128.
// ---------------------------------------------------------------------------
__global__ __launch_bounds__(256) void rnn_step_kernel(
    const float* __restrict__ H,    // [BATCH, DIM] previous hidden
    const float* __restrict__ W,    // Wh [DIM, DIM]
    float* __restrict__ out,        // [BATCH, DIM] = hs[t]
    int t)
{
    const int BM = 32, BN = 32, BK = 32, PAD = 36;
    __shared__ float As[BK][PAD];   // transposed: As[k][m]
    __shared__ float Bs[BK][PAD];   // Bs[k][n]

    const int bx = blockIdx.x;      // N tile (0..31)
    const int by = blockIdx.y;      // M tile (0..3)
    const int tid = threadIdx.x;
    const int tr = tid >> 4;        // 0..15
    const int tc = tid & 15;        // 0..15
    const int row0 = by * BM;
    const int col0 = bx * BN;

    float acc[2][2] = {};

    for (int k0 = 0; k0 < DIM; k0 += BK) {
        // Load A tile: 32 rows x 32 k, one float4 per thread, transposed store.
        {
            const int m  = tid >> 3;          // 0..31
            const int kq = (tid & 7) << 2;    // 0..28
            float4 v = *reinterpret_cast<const float4*>(
                &H[(size_t)(row0 + m) * DIM + k0 + kq]);
            As[kq + 0][m] = v.x;
            As[kq + 1][m] = v.y;
            As[kq + 2][m] = v.z;
            As[kq + 3][m] = v.w;
        }
        // Load B tile: 32 k x 32 n, one float4 per thread.
        {
            const int kr = tid >> 3;          // 0..31
            const int nq = (tid & 7) << 2;    // 0..28
            float4 v = *reinterpret_cast<const float4*>(
                &W[(size_t)(k0 + kr) * DIM + col0 + nq]);
            *reinterpret_cast<float4*>(&Bs[kr][nq]) = v;   // 144B row stride -> 16B aligned
        }
        __syncthreads();

        #pragma unroll
        for (int k = 0; k < BK; k++) {
            float2 a  = *reinterpret_cast<const float2*>(&As[k][tr << 1]);
            float2 bv = *reinterpret_cast<const float2*>(&Bs[k][tc << 1]);
            acc[0][0] += a.x * bv.x;
            acc[0][1] += a.x * bv.y;
            acc[1][0] += a.y * bv.x;
            acc[1][1] += a.y * bv.y;
        }
        __syncthreads();
    }

    const float* xp_t = g_xp + (size_t)t * BATCH * DIM;
    #pragma unroll
    for (int i = 0; i < 2; i++) {
        const int r = row0 + (tr << 1) + i;
        #pragma unroll
        for (int j = 0; j < 2; j++) {
            const int c = col0 + (tc << 1) + j;
            out[(size_t)r * DIM + c] = tanhf(acc[i][j] + xp_t[(size_t)r * DIM + c]);
        }
    }
}

// ---------------------------------------------------------------------------
// Launcher: inputs in metadata order: x, h0, Wx, Wh, b
// ---------------------------------------------------------------------------
extern "C" void kernel_launch(void* const* d_in, const int* in_sizes, int n_in,
                              void* d_out, int out_size)
{
    const float* x  = (const float*)d_in[0];  // [SEQ, BATCH, DIM]
    const float* h0 = (const float*)d_in[1];  // [BATCH, DIM]
    const float* Wx = (const float*)d_in[2];  // [DIM, DIM]
    const float* Wh = (const float*)d_in[3];  // [DIM, DIM]
    const float* b  = (const float*)d_in[4];  // [DIM]
    float* out = (float*)d_out;               // [SEQ, BATCH, DIM]

    // 1) xp = x @ Wx + b   (M = SEQ*BATCH = 16384)
    {
        dim3 grid(DIM / 64, (SEQ * BATCH) / 64);  // 16 x 256
        gemm_xp_kernel<<<grid, 256>>>(x, Wx, b);
    }

    // 2) 128 sequential steps: h_t = tanh(xp[t] + h_{t-1} @ Wh)
    {
        dim3 grid(DIM / 32, BATCH / 32);          // 32 x 4 = 128 blocks
        const float* prev = h0;
        for (int t = 0; t < SEQ; t++) {
            float* ht = out + (size_t)t * BATCH * DIM;
            rnn_step_kernel<<<grid, 256>>>(prev, Wh, ht, t);
            prev = ht;
        }
    }
}

// round 5
// speedup vs baseline: 1.1932x; 1.1932x over previous
#include <cuda_runtime.h>
#include <cuda_bf16.h>
#include <math.h>
#include <stdint.h>

#define SEQ 128
#define BATCH 128
#define DIM 1024
#define KD2 (DIM / 2)          // u32 (bf16x2) per row

#define GRID_R 128             // persistent CTAs for recurrence (<=148, all co-resident)
#define THREADS_R 256

// ---------------------------------------------------------------------------
// Global scratch (allocations are forbidden)
// ---------------------------------------------------------------------------
__device__ float g_xp[(size_t)SEQ * BATCH * DIM];        // x @ Wx + b
__device__ __nv_bfloat16 g_hh[2][BATCH * DIM];           // H hi, ping-pong
__device__ __nv_bfloat16 g_hl[2][BATCH * DIM];           // H lo, ping-pong
__device__ unsigned g_arrive[GRID_R * 32];               // 128B-strided flags
__device__ unsigned g_release;

// ---------------------------------------------------------------------------
// Helpers
// ---------------------------------------------------------------------------
__device__ __forceinline__ void split2(float v, unsigned short& hi, unsigned short& lo) {
    __nv_bfloat16 h = __float2bfloat16(v);
    __nv_bfloat16 l = __float2bfloat16(v - __bfloat162float(h));
    hi = __bfloat16_as_ushort(h);
    lo = __bfloat16_as_ushort(l);
}
__device__ __forceinline__ unsigned pck(unsigned short a, unsigned short b) {
    return ((unsigned)b << 16) | (unsigned)a;   // a -> low halfword (even col)
}

// D += A(bf16,row) x B(bf16,col), m16n8k16, fp32 accum
__device__ __forceinline__ void mma_bf16(float c[4],
                                         unsigned a0, unsigned a1, unsigned a2, unsigned a3,
                                         unsigned b0, unsigned b1) {
    asm volatile(
        "mma.sync.aligned.m16n8k16.row.col.f32.bf16.bf16.f32 "
        "{%0,%1,%2,%3}, {%4,%5,%6,%7}, {%8,%9}, {%0,%1,%2,%3};"
        : "+f"(c[0]), "+f"(c[1]), "+f"(c[2]), "+f"(c[3])
        : "r"(a0), "r"(a1), "r"(a2), "r"(a3), "r"(b0), "r"(b1));
}

// ---------------------------------------------------------------------------
// Kernel 1: xp = X @ Wx + b   [16384 x 1024], split-bf16 HMMA
// Tiles: BM=64, BN=64, BK=64; 256 threads; warp = 16 rows x 32 cols.
// ---------------------------------------------------------------------------
__global__ __launch_bounds__(256) void gemm_xp_mma(
    const float* __restrict__ X,
    const float* __restrict__ W,
    const float* __restrict__ bias)
{
    __shared__ unsigned short Ahi[64][72], Alo[64][72];  // [m][k], 144B rows
    __shared__ unsigned short Bhi[64][72], Blo[64][72];  // [n][k]

    const int tid = threadIdx.x, lane = tid & 31, wid = tid >> 5;
    const int m0 = blockIdx.y * 64, n0 = blockIdx.x * 64;
    const int g = lane >> 2, t4 = lane & 3;
    const int mt = wid >> 1;     // 0..3 : 16-row tile
    const int nh = wid & 1;      // 0..1 : 32-col half

    const int lrow = tid >> 2;           // 0..63
    const int lcb  = (tid & 3) * 16;     // 0,16,32,48

    float acc[4][4] = {};

    for (int k0 = 0; k0 < DIM; k0 += 64) {
        __syncthreads();
        // ---- load & split A tile (64m x 64k fp32) ----
        #pragma unroll
        for (int j = 0; j < 4; j++) {
            float4 v = *reinterpret_cast<const float4*>(
                &X[(size_t)(m0 + lrow) * DIM + k0 + lcb + j * 4]);
            unsigned short h, l;
            const int c = lcb + j * 4;
            split2(v.x, h, l); Ahi[lrow][c + 0] = h; Alo[lrow][c + 0] = l;
            split2(v.y, h, l); Ahi[lrow][c + 1] = h; Alo[lrow][c + 1] = l;
            split2(v.z, h, l); Ahi[lrow][c + 2] = h; Alo[lrow][c + 2] = l;
            split2(v.w, h, l); Ahi[lrow][c + 3] = h; Alo[lrow][c + 3] = l;
        }
        // ---- load & split B tile (64k x 64n fp32), store transposed [n][k] ----
        #pragma unroll
        for (int j = 0; j < 4; j++) {
            float4 v = *reinterpret_cast<const float4*>(
                &W[(size_t)(k0 + lrow) * DIM + n0 + lcb + j * 4]);
            unsigned short h, l;
            const int n = lcb + j * 4;
            split2(v.x, h, l); Bhi[n + 0][lrow] = h; Blo[n + 0][lrow] = l;
            split2(v.y, h, l); Bhi[n + 1][lrow] = h; Blo[n + 1][lrow] = l;
            split2(v.z, h, l); Bhi[n + 2][lrow] = h; Blo[n + 2][lrow] = l;
            split2(v.w, h, l); Bhi[n + 3][lrow] = h; Blo[n + 3][lrow] = l;
        }
        __syncthreads();

        // ---- 4 k-steps of m16n8k16 ----
        #pragma unroll
        for (int ks = 0; ks < 4; ks++) {
            const int ka = ks * 16 + 2 * t4;
            const int ar0 = mt * 16 + g, ar1 = ar0 + 8;
            unsigned ah0 = *(const unsigned*)&Ahi[ar0][ka];
            unsigned ah1 = *(const unsigned*)&Ahi[ar1][ka];
            unsigned ah2 = *(const unsigned*)&Ahi[ar0][ka + 8];
            unsigned ah3 = *(const unsigned*)&Ahi[ar1][ka + 8];
            unsigned al0 = *(const unsigned*)&Alo[ar0][ka];
            unsigned al1 = *(const unsigned*)&Alo[ar1][ka];
            unsigned al2 = *(const unsigned*)&Alo[ar0][ka + 8];
            unsigned al3 = *(const unsigned*)&Alo[ar1][ka + 8];
            #pragma unroll
            for (int nt = 0; nt < 4; nt++) {
                const int n = nh * 32 + nt * 8 + g;
                unsigned bh0 = *(const unsigned*)&Bhi[n][ka];
                unsigned bh1 = *(const unsigned*)&Bhi[n][ka + 8];
                unsigned bl0 = *(const unsigned*)&Blo[n][ka];
                unsigned bl1 = *(const unsigned*)&Blo[n][ka + 8];
                mma_bf16(acc[nt], ah0, ah1, ah2, ah3, bh0, bh1);
                mma_bf16(acc[nt], ah0, ah1, ah2, ah3, bl0, bl1);
                mma_bf16(acc[nt], al0, al1, al2, al3, bh0, bh1);
            }
        }
    }

    // ---- epilogue: + bias, write fp32 ----
    #pragma unroll
    for (int nt = 0; nt < 4; nt++) {
        const int col = n0 + nh * 32 + nt * 8 + 2 * t4;
        const int r0 = m0 + mt * 16 + g;
        float2 bb = *reinterpret_cast<const float2*>(&bias[col]);
        float2 v0 = { acc[nt][0] + bb.x, acc[nt][1] + bb.y };
        float2 v1 = { acc[nt][2] + bb.x, acc[nt][3] + bb.y };
        *reinterpret_cast<float2*>(&g_xp[(size_t)r0 * DIM + col]) = v0;
        *reinterpret_cast<float2*>(&g_xp[(size_t)(r0 + 8) * DIM + col]) = v1;
    }
}

// ---------------------------------------------------------------------------
// Grid barrier: flags + release word (all GRID_R CTAs co-resident)
// ---------------------------------------------------------------------------
__device__ __forceinline__ void gbar(unsigned e) {
    __threadfence();
    __syncthreads();
    if (blockIdx.x == 0) {
        if (threadIdx.x > 0 && threadIdx.x < GRID_R) {
            while (*(volatile unsigned*)&g_arrive[threadIdx.x * 32] < e) { }
        }
        __syncthreads();
        if (threadIdx.x == 0) { __threadfence(); g_release = e; }
    } else {
        if (threadIdx.x == 0) {
            *(volatile unsigned*)&g_arrive[blockIdx.x * 32] = e;
            while (*(volatile unsigned*)&g_release < e) { }
        }
    }
    __syncthreads();
    __threadfence();
}

// ---------------------------------------------------------------------------
// Kernel 2: persistent recurrence, h_t = tanh(xp[t] + h_{t-1} @ Wh)
// 128 CTAs x (32 rows x 32 cols). Wh strip pre-packed as MMA fragments in smem.
// Dynamic smem: whp_hi[8192] + whp_lo[8192] uint2 = 128 KB.
// ---------------------------------------------------------------------------
__global__ __launch_bounds__(THREADS_R, 1) void rnn_rec_kernel(
    const float* __restrict__ h0,
    const float* __restrict__ Wh,
    float* __restrict__ out)
{
    extern __shared__ uint2 s_whp[];
    uint2* whp_hi = s_whp;            // [ (ks*4 + nt)*32 + lane ]
    uint2* whp_lo = s_whp + 8192;

    const int tid = threadIdx.x, lane = tid & 31, wid = tid >> 5;
    const int g = lane >> 2, t4 = lane & 3;
    const int mblk = blockIdx.x >> 5;        // 0..3
    const int nstrip = blockIdx.x & 31;      // 0..31
    const int m0 = mblk * 32, n0 = nstrip * 32;
    const int mt = wid >> 2;                 // 0..1
    const int nt = wid & 3;                  // 0..3

    // ---- prologue: pack Wh strip into fragment order (once) ----
    for (int idx = tid; idx < 8192; idx += THREADS_R) {
        const int ks = idx >> 7;
        const int nti = (idx >> 5) & 3;
        const int ln = idx & 31;
        const int gg = ln >> 2, tt = ln & 3;
        const int n = n0 + nti * 8 + gg;
        const int kb = ks * 16 + 2 * tt;
        float w00 = __ldg(&Wh[(size_t)(kb + 0) * DIM + n]);
        float w01 = __ldg(&Wh[(size_t)(kb + 1) * DIM + n]);
        float w10 = __ldg(&Wh[(size_t)(kb + 8) * DIM + n]);
        float w11 = __ldg(&Wh[(size_t)(kb + 9) * DIM + n]);
        unsigned short h00, l00, h01, l01, h10, l10, h11, l11;
        split2(w00, h00, l00); split2(w01, h01, l01);
        split2(w10, h10, l10); split2(w11, h11, l11);
        whp_hi[idx] = make_uint2(pck(h00, h01), pck(h10, h11));
        whp_lo[idx] = make_uint2(pck(l00, l01), pck(l10, l11));
    }

    // ---- initial H = h0, split into buffer 0 ----
    for (int i = blockIdx.x * THREADS_R + tid; i < BATCH * DIM; i += GRID_R * THREADS_R) {
        unsigned short hi, lo;
        split2(h0[i], hi, lo);
        g_hh[0][i] = __ushort_as_bfloat16(hi);
        g_hl[0][i] = __ushort_as_bfloat16(lo);
    }
    unsigned ep = 1;
    gbar(ep);

    const int r0 = m0 + mt * 16 + g;         // this lane's row 0 (row 1 = +8)
    const int col = n0 + nt * 8 + 2 * t4;    // this lane's col pair

    for (int t = 0; t < SEQ; t++) {
        const int rb = t & 1, wb = rb ^ 1;
        const unsigned* Hh = reinterpret_cast<const unsigned*>(g_hh[rb]);
        const unsigned* Hl = reinterpret_cast<const unsigned*>(g_hl[rb]);
        const unsigned* hh0 = Hh + (size_t)r0 * KD2;
        const unsigned* hh1 = Hh + (size_t)(r0 + 8) * KD2;
        const unsigned* hl0 = Hl + (size_t)r0 * KD2;
        const unsigned* hl1 = Hl + (size_t)(r0 + 8) * KD2;
        const uint2* bph = whp_hi + nt * 32 + lane;
        const uint2* bpl = whp_lo + nt * 32 + lane;

        float c[4] = {0.f, 0.f, 0.f, 0.f};

        #pragma unroll 4
        for (int ks = 0; ks < 64; ks++) {
            const int kb = ks * 8 + t4;
            unsigned ah0 = __ldcg(hh0 + kb);
            unsigned ah1 = __ldcg(hh1 + kb);
            unsigned ah2 = __ldcg(hh0 + kb + 4);
            unsigned ah3 = __ldcg(hh1 + kb + 4);
            unsigned al0 = __ldcg(hl0 + kb);
            unsigned al1 = __ldcg(hl1 + kb);
            unsigned al2 = __ldcg(hl0 + kb + 4);
            unsigned al3 = __ldcg(hl1 + kb + 4);
            uint2 bh = bph[ks * 128];
            uint2 bl = bpl[ks * 128];
            mma_bf16(c, ah0, ah1, ah2, ah3, bh.x, bh.y);
            mma_bf16(c, ah0, ah1, ah2, ah3, bl.x, bl.y);
            mma_bf16(c, al0, al1, al2, al3, bh.x, bh.y);
        }

        // ---- epilogue: +xp, tanh, write out (fp32) + next H (bf16 split) ----
        {
            const size_t ob0 = ((size_t)t * BATCH + r0) * DIM + col;
            const size_t ob1 = ((size_t)t * BATCH + r0 + 8) * DIM + col;
            float2 x0 = *reinterpret_cast<const float2*>(&g_xp[ob0]);
            float2 x1 = *reinterpret_cast<const float2*>(&g_xp[ob1]);
            float v0 = tanhf(c[0] + x0.x), v1 = tanhf(c[1] + x0.y);
            float v2 = tanhf(c[2] + x1.x), v3 = tanhf(c[3] + x1.y);
            float2 o0 = {v0, v1}, o1 = {v2, v3};
            *reinterpret_cast<float2*>(&out[ob0]) = o0;
            *reinterpret_cast<float2*>(&out[ob1]) = o1;
            unsigned short h0s, l0s, h1s, l1s;
            unsigned* HHn = reinterpret_cast<unsigned*>(g_hh[wb]);
            unsigned* HLn = reinterpret_cast<unsigned*>(g_hl[wb]);
            const int ci = col >> 1;
            split2(v0, h0s, l0s); split2(v1, h1s, l1s);
            HHn[(size_t)r0 * KD2 + ci] = pck(h0s, h1s);
            HLn[(size_t)r0 * KD2 + ci] = pck(l0s, l1s);
            split2(v2, h0s, l0s); split2(v3, h1s, l1s);
            HHn[(size_t)(r0 + 8) * KD2 + ci] = pck(h0s, h1s);
            HLn[(size_t)(r0 + 8) * KD2 + ci] = pck(l0s, l1s);
        }
        gbar(++ep);
    }
}

// ---------------------------------------------------------------------------
// Launcher: inputs: x, h0, Wx, Wh, b
// ---------------------------------------------------------------------------
extern "C" void kernel_launch(void* const* d_in, const int* in_sizes, int n_in,
                              void* d_out, int out_size)
{
    const float* x  = (const float*)d_in[0];
    const float* h0 = (const float*)d_in[1];
    const float* Wx = (const float*)d_in[2];
    const float* Wh = (const float*)d_in[3];
    const float* b  = (const float*)d_in[4];
    float* out = (float*)d_out;

    static int s_attr_done = 0;
    if (!s_attr_done) {
        cudaFuncSetAttribute(rnn_rec_kernel,
                             cudaFuncAttributeMaxDynamicSharedMemorySize, 131072);
        s_attr_done = 1;
    }

    // reset barrier state (graph-capturable async memsets)
    void* a0 = nullptr; void* a1 = nullptr;
    cudaGetSymbolAddress(&a0, g_arrive);
    cudaGetSymbolAddress(&a1, g_release);
    cudaMemsetAsync(a0, 0, GRID_R * 32 * sizeof(unsigned));
    cudaMemsetAsync(a1, 0, sizeof(unsigned));

    // 1) xp = x @ Wx + b  (tensor cores, split-bf16)
    {
        dim3 grid(DIM / 64, (SEQ * BATCH) / 64);   // 16 x 256
        gemm_xp_mma<<<grid, 256>>>(x, Wx, b);
    }
    // 2) persistent recurrence (tensor cores, split-bf16), all 128 steps
    rnn_rec_kernel<<<GRID_R, THREADS_R, 131072>>>(h0, Wh, out);
}

// round 8
// speedup vs baseline: 2.3250x; 1.9485x over previous
#include <cuda_runtime.h>
#include <cuda_bf16.h>
#include <math.h>
#include <stdint.h>

#define SEQ 128
#define BATCH 128
#define DIM 1024
#define KD2 (DIM / 2)

#define GRID_R 128
#define THREADS_R 256

#define CHUNK 256                 // K elements per staged chunk
#define NCH (DIM / CHUNK)         // 4
#define SROW 264                  // padded A row stride (elements); 528B = 33*16
#define AHALF (32 * SROW)         // elements per (slot,half)
#define ASLOT (2 * AHALF)
#define WHP_BYTES 131072
#define DYN_BYTES (WHP_BYTES + 2 * ASLOT * 2)   // + 2 slots * bf16

// ---------------------------------------------------------------------------
// Global scratch
// ---------------------------------------------------------------------------
__device__ float g_xp[(size_t)SEQ * BATCH * DIM];
__device__ __nv_bfloat16 g_hh[2][BATCH * DIM];
__device__ __nv_bfloat16 g_hl[2][BATCH * DIM];
__device__ unsigned g_arrive[GRID_R * 32];
__device__ unsigned g_release;

// ---------------------------------------------------------------------------
// Helpers
// ---------------------------------------------------------------------------
__device__ __forceinline__ void split2(float v, unsigned short& hi, unsigned short& lo) {
    __nv_bfloat16 h = __float2bfloat16(v);
    __nv_bfloat16 l = __float2bfloat16(v - __bfloat162float(h));
    hi = __bfloat16_as_ushort(h);
    lo = __bfloat16_as_ushort(l);
}
__device__ __forceinline__ unsigned pck(unsigned short a, unsigned short b) {
    return ((unsigned)b << 16) | (unsigned)a;
}
__device__ __forceinline__ uint32_t smem_u32(const void* p) {
    uint32_t a;
    asm("{ .reg .u64 t; cvta.to.shared.u64 t, %1; cvt.u32.u64 %0, t; }"
        : "=r"(a) : "l"(p));
    return a;
}
__device__ __forceinline__ void mma_bf16(float c[4],
                                         unsigned a0, unsigned a1, unsigned a2, unsigned a3,
                                         unsigned b0, unsigned b1) {
    asm volatile(
        "mma.sync.aligned.m16n8k16.row.col.f32.bf16.bf16.f32 "
        "{%0,%1,%2,%3}, {%4,%5,%6,%7}, {%8,%9}, {%0,%1,%2,%3};"
        : "+f"(c[0]), "+f"(c[1]), "+f"(c[2]), "+f"(c[3])
        : "r"(a0), "r"(a1), "r"(a2), "r"(a3), "r"(b0), "r"(b1));
}
__device__ __forceinline__ void ldsm4(unsigned& r0, unsigned& r1, unsigned& r2, unsigned& r3,
                                      uint32_t addr) {
    asm volatile("ldmatrix.sync.aligned.m8n8.x4.shared.b16 {%0,%1,%2,%3}, [%4];"
                 : "=r"(r0), "=r"(r1), "=r"(r2), "=r"(r3) : "r"(addr));
}
__device__ __forceinline__ void cp16(uint32_t dst, const void* src) {
    asm volatile("cp.async.cg.shared.global [%0], [%1], 16;" :: "r"(dst), "l"(src));
}
#define CP_COMMIT() asm volatile("cp.async.commit_group;" ::: "memory")
#define CP_WAIT(n)  asm volatile("cp.async.wait_group %0;" :: "n"(n) : "memory")

// ---------------------------------------------------------------------------
// Kernel 1: xp = X @ Wx + b  (unchanged from passing round)
// ---------------------------------------------------------------------------
__global__ __launch_bounds__(256) void gemm_xp_mma(
    const float* __restrict__ X,
    const float* __restrict__ W,
    const float* __restrict__ bias)
{
    __shared__ unsigned short Ahi[64][72], Alo[64][72];
    __shared__ unsigned short Bhi[64][72], Blo[64][72];

    const int tid = threadIdx.x, lane = tid & 31, wid = tid >> 5;
    const int m0 = blockIdx.y * 64, n0 = blockIdx.x * 64;
    const int g = lane >> 2, t4 = lane & 3;
    const int mt = wid >> 1;
    const int nh = wid & 1;

    const int lrow = tid >> 2;
    const int lcb  = (tid & 3) * 16;

    float acc[4][4] = {};

    for (int k0 = 0; k0 < DIM; k0 += 64) {
        __syncthreads();
        #pragma unroll
        for (int j = 0; j < 4; j++) {
            float4 v = *reinterpret_cast<const float4*>(
                &X[(size_t)(m0 + lrow) * DIM + k0 + lcb + j * 4]);
            unsigned short h, l;
            const int c = lcb + j * 4;
            split2(v.x, h, l); Ahi[lrow][c + 0] = h; Alo[lrow][c + 0] = l;
            split2(v.y, h, l); Ahi[lrow][c + 1] = h; Alo[lrow][c + 1] = l;
            split2(v.z, h, l); Ahi[lrow][c + 2] = h; Alo[lrow][c + 2] = l;
            split2(v.w, h, l); Ahi[lrow][c + 3] = h; Alo[lrow][c + 3] = l;
        }
        #pragma unroll
        for (int j = 0; j < 4; j++) {
            float4 v = *reinterpret_cast<const float4*>(
                &W[(size_t)(k0 + lrow) * DIM + n0 + lcb + j * 4]);
            unsigned short h, l;
            const int n = lcb + j * 4;
            split2(v.x, h, l); Bhi[n + 0][lrow] = h; Blo[n + 0][lrow] = l;
            split2(v.y, h, l); Bhi[n + 1][lrow] = h; Blo[n + 1][lrow] = l;
            split2(v.z, h, l); Bhi[n + 2][lrow] = h; Blo[n + 2][lrow] = l;
            split2(v.w, h, l); Bhi[n + 3][lrow] = h; Blo[n + 3][lrow] = l;
        }
        __syncthreads();

        #pragma unroll
        for (int ks = 0; ks < 4; ks++) {
            const int ka = ks * 16 + 2 * t4;
            const int ar0 = mt * 16 + g, ar1 = ar0 + 8;
            unsigned ah0 = *(const unsigned*)&Ahi[ar0][ka];
            unsigned ah1 = *(const unsigned*)&Ahi[ar1][ka];
            unsigned ah2 = *(const unsigned*)&Ahi[ar0][ka + 8];
            unsigned ah3 = *(const unsigned*)&Ahi[ar1][ka + 8];
            unsigned al0 = *(const unsigned*)&Alo[ar0][ka];
            unsigned al1 = *(const unsigned*)&Alo[ar1][ka];
            unsigned al2 = *(const unsigned*)&Alo[ar0][ka + 8];
            unsigned al3 = *(const unsigned*)&Alo[ar1][ka + 8];
            #pragma unroll
            for (int nt = 0; nt < 4; nt++) {
                const int n = nh * 32 + nt * 8 + g;
                unsigned bh0 = *(const unsigned*)&Bhi[n][ka];
                unsigned bh1 = *(const unsigned*)&Bhi[n][ka + 8];
                unsigned bl0 = *(const unsigned*)&Blo[n][ka];
                unsigned bl1 = *(const unsigned*)&Blo[n][ka + 8];
                mma_bf16(acc[nt], ah0, ah1, ah2, ah3, bh0, bh1);
                mma_bf16(acc[nt], ah0, ah1, ah2, ah3, bl0, bl1);
                mma_bf16(acc[nt], al0, al1, al2, al3, bh0, bh1);
            }
        }
    }

    #pragma unroll
    for (int nt = 0; nt < 4; nt++) {
        const int col = n0 + nh * 32 + nt * 8 + 2 * t4;
        const int r0 = m0 + mt * 16 + g;
        float2 bb = *reinterpret_cast<const float2*>(&bias[col]);
        float2 v0 = { acc[nt][0] + bb.x, acc[nt][1] + bb.y };
        float2 v1 = { acc[nt][2] + bb.x, acc[nt][3] + bb.y };
        *reinterpret_cast<float2*>(&g_xp[(size_t)r0 * DIM + col]) = v0;
        *reinterpret_cast<float2*>(&g_xp[(size_t)(r0 + 8) * DIM + col]) = v1;
    }
}

// ---------------------------------------------------------------------------
// Grid barrier
// ---------------------------------------------------------------------------
__device__ __forceinline__ void gbar(unsigned e) {
    __threadfence();
    __syncthreads();
    if (blockIdx.x == 0) {
        if (threadIdx.x > 0 && threadIdx.x < GRID_R) {
            while (*(volatile unsigned*)&g_arrive[threadIdx.x * 32] < e) { }
        }
        __syncthreads();
        if (threadIdx.x == 0) { __threadfence(); g_release = e; }
    } else {
        if (threadIdx.x == 0) {
            *(volatile unsigned*)&g_arrive[blockIdx.x * 32] = e;
            while (*(volatile unsigned*)&g_release < e) { }
        }
    }
    __syncthreads();
    __threadfence();
}

// ---------------------------------------------------------------------------
// Kernel 2: persistent recurrence with smem-staged A + ldmatrix
// Dynamic smem:
//   [0, 64K)    whp_hi  uint2[8192]   packed Wh hi fragments
//   [64K,128K)  whp_lo  uint2[8192]
//   [128K, +66K) A stage bf16 [2 slots][2 halves][32 rows][264]
// ---------------------------------------------------------------------------
__global__ __launch_bounds__(THREADS_R, 1) void rnn_rec_kernel(
    const float* __restrict__ h0,
    const float* __restrict__ Wh,
    float* __restrict__ out)
{
    extern __shared__ char s_dyn[];
    uint2* whp_hi = reinterpret_cast<uint2*>(s_dyn);
    uint2* whp_lo = whp_hi + 8192;
    __nv_bfloat16* s_a = reinterpret_cast<__nv_bfloat16*>(s_dyn + WHP_BYTES);
    const uint32_t s_a_u32 = smem_u32(s_a);

    const int tid = threadIdx.x, lane = tid & 31, wid = tid >> 5;
    const int g = lane >> 2, t4 = lane & 3;
    const int mblk = blockIdx.x >> 5;
    const int nstrip = blockIdx.x & 31;
    const int m0 = mblk * 32, n0 = nstrip * 32;
    const int mt = wid >> 2;                 // 0..1
    const int nt = wid & 3;                  // 0..3

    // ---- pack Wh strip into fragment order (once) ----
    for (int idx = tid; idx < 8192; idx += THREADS_R) {
        const int ks = idx >> 7;
        const int nti = (idx >> 5) & 3;
        const int ln = idx & 31;
        const int gg = ln >> 2, tt = ln & 3;
        const int n = n0 + nti * 8 + gg;
        const int kb = ks * 16 + 2 * tt;
        float w00 = __ldg(&Wh[(size_t)(kb + 0) * DIM + n]);
        float w01 = __ldg(&Wh[(size_t)(kb + 1) * DIM + n]);
        float w10 = __ldg(&Wh[(size_t)(kb + 8) * DIM + n]);
        float w11 = __ldg(&Wh[(size_t)(kb + 9) * DIM + n]);
        unsigned short h00, l00, h01, l01, h10, l10, h11, l11;
        split2(w00, h00, l00); split2(w01, h01, l01);
        split2(w10, h10, l10); split2(w11, h11, l11);
        whp_hi[idx] = make_uint2(pck(h00, h01), pck(h10, h11));
        whp_lo[idx] = make_uint2(pck(l00, l01), pck(l10, l11));
    }

    // ---- initial H = h0, split into buffer 0 ----
    for (int i = blockIdx.x * THREADS_R + tid; i < BATCH * DIM; i += GRID_R * THREADS_R) {
        unsigned short hi, lo;
        split2(h0[i], hi, lo);
        g_hh[0][i] = __ushort_as_bfloat16(hi);
        g_hl[0][i] = __ushort_as_bfloat16(lo);
    }
    unsigned ep = 1;
    gbar(ep);

    const int r0 = m0 + mt * 16 + g;
    const int col = n0 + nt * 8 + 2 * t4;

    // ldmatrix per-lane address components (within a slot/half)
    const int arow = mt * 16 + (lane & 15);
    const int acol = (lane >> 4) * 8;
    const uint32_t a_lane_off = (uint32_t)(arow * SROW + acol) * 2;

    const uint2* bh_ptr = whp_hi + nt * 32 + lane;
    const uint2* bl_ptr = whp_lo + nt * 32 + lane;

    for (int t = 0; t < SEQ; t++) {
        const int rb = t & 1, wb = rb ^ 1;
        const __nv_bfloat16* Hh = g_hh[rb];
        const __nv_bfloat16* Hl = g_hl[rb];

        float c[4] = {0.f, 0.f, 0.f, 0.f};

        // ---- prologue: stage chunk 0 ----
        {
            #pragma unroll
            for (int i = 0; i < 8; i++) {
                const int idx = tid + i * THREADS_R;
                const int half = idx >> 10;
                const int rem = idx & 1023;
                const int row = rem >> 5, seg = rem & 31;
                const __nv_bfloat16* src =
                    (half ? Hl : Hh) + (size_t)(m0 + row) * DIM + seg * 8;
                const uint32_t dst = s_a_u32 +
                    (uint32_t)(half * AHALF + row * SROW + seg * 8) * 2;
                cp16(dst, src);
            }
            CP_COMMIT();
        }

        #pragma unroll
        for (int ch = 0; ch < NCH; ch++) {
            const int slot = ch & 1;
            if (ch + 1 < NCH) {
                const int nslot = slot ^ 1;
                const int k0 = (ch + 1) * CHUNK;
                #pragma unroll
                for (int i = 0; i < 8; i++) {
                    const int idx = tid + i * THREADS_R;
                    const int half = idx >> 10;
                    const int rem = idx & 1023;
                    const int row = rem >> 5, seg = rem & 31;
                    const __nv_bfloat16* src =
                        (half ? Hl : Hh) + (size_t)(m0 + row) * DIM + k0 + seg * 8;
                    const uint32_t dst = s_a_u32 +
                        (uint32_t)(nslot * ASLOT + half * AHALF + row * SROW + seg * 8) * 2;
                    cp16(dst, src);
                }
                CP_COMMIT();
                CP_WAIT(1);
            } else {
                CP_WAIT(0);
            }
            __syncthreads();

            const uint32_t a_hi_base = s_a_u32 + (uint32_t)(slot * ASLOT) * 2 + a_lane_off;
            const uint32_t a_lo_base = a_hi_base + (uint32_t)AHALF * 2;

            #pragma unroll
            for (int ks = 0; ks < CHUNK / 16; ks++) {
                unsigned ah0, ah1, ah2, ah3, al0, al1, al2, al3;
                ldsm4(ah0, ah1, ah2, ah3, a_hi_base + ks * 32);
                ldsm4(al0, al1, al2, al3, a_lo_base + ks * 32);
                const int ksg = ch * (CHUNK / 16) + ks;
                uint2 bh = bh_ptr[ksg * 128];
                uint2 bl = bl_ptr[ksg * 128];
                mma_bf16(c, ah0, ah1, ah2, ah3, bh.x, bh.y);
                mma_bf16(c, ah0, ah1, ah2, ah3, bl.x, bl.y);
                mma_bf16(c, al0, al1, al2, al3, bh.x, bh.y);
            }
            __syncthreads();
        }

        // ---- epilogue: +xp, tanh, write out + next H ----
        {
            const size_t ob0 = ((size_t)t * BATCH + r0) * DIM + col;
            const size_t ob1 = ((size_t)t * BATCH + r0 + 8) * DIM + col;
            float2 x0 = *reinterpret_cast<const float2*>(&g_xp[ob0]);
            float2 x1 = *reinterpret_cast<const float2*>(&g_xp[ob1]);
            float v0 = tanhf(c[0] + x0.x), v1 = tanhf(c[1] + x0.y);
            float v2 = tanhf(c[2] + x1.x), v3 = tanhf(c[3] + x1.y);
            float2 o0 = {v0, v1}, o1 = {v2, v3};
            *reinterpret_cast<float2*>(&out[ob0]) = o0;
            *reinterpret_cast<float2*>(&out[ob1]) = o1;
            unsigned short hs0, ls0, hs1, ls1;
            unsigned* HHn = reinterpret_cast<unsigned*>(g_hh[wb]);
            unsigned* HLn = reinterpret_cast<unsigned*>(g_hl[wb]);
            const int ci = col >> 1;
            split2(v0, hs0, ls0); split2(v1, hs1, ls1);
            HHn[(size_t)r0 * KD2 + ci] = pck(hs0, hs1);
            HLn[(size_t)r0 * KD2 + ci] = pck(ls0, ls1);
            split2(v2, hs0, ls0); split2(v3, hs1, ls1);
            HHn[(size_t)(r0 + 8) * KD2 + ci] = pck(hs0, hs1);
            HLn[(size_t)(r0 + 8) * KD2 + ci] = pck(ls0, ls1);
        }
        gbar(++ep);
    }
}

// ---------------------------------------------------------------------------
// Launcher: inputs: x, h0, Wx, Wh, b
// ---------------------------------------------------------------------------
extern "C" void kernel_launch(void* const* d_in, const int* in_sizes, int n_in,
                              void* d_out, int out_size)
{
    const float* x  = (const float*)d_in[0];
    const float* h0 = (const float*)d_in[1];
    const float* Wx = (const float*)d_in[2];
    const float* Wh = (const float*)d_in[3];
    const float* b  = (const float*)d_in[4];
    float* out = (float*)d_out;

    static int s_attr_done = 0;
    if (!s_attr_done) {
        cudaFuncSetAttribute(rnn_rec_kernel,
                             cudaFuncAttributeMaxDynamicSharedMemorySize, DYN_BYTES);
        s_attr_done = 1;
    }

    void* a0 = nullptr; void* a1 = nullptr;
    cudaGetSymbolAddress(&a0, g_arrive);
    cudaGetSymbolAddress(&a1, g_release);
    cudaMemsetAsync(a0, 0, GRID_R * 32 * sizeof(unsigned));
    cudaMemsetAsync(a1, 0, sizeof(unsigned));

    {
        dim3 grid(DIM / 64, (SEQ * BATCH) / 64);
        gemm_xp_mma<<<grid, 256>>>(x, Wx, b);
    }
    rnn_rec_kernel<<<GRID_R, THREADS_R, DYN_BYTES>>>(h0, Wh, out);
}

// round 9
// speedup vs baseline: 3.3874x; 1.4570x over previous
#include <cuda_runtime.h>
#include <cuda_bf16.h>
#include <math.h>
#include <stdint.h>

#define SEQ 128
#define BATCH 128
#define DIM 1024
#define KD2 (DIM / 2)

#define GRID_R 128
#define THREADS_R 256

#define CHUNK 256
#define NCH (DIM / CHUNK)
#define SROW 264
#define AHALF (32 * SROW)
#define ASLOT (2 * AHALF)
#define WHP_BYTES 131072
#define DYN_BYTES (WHP_BYTES + 2 * ASLOT * 2)

// ---------------------------------------------------------------------------
// Global scratch
// ---------------------------------------------------------------------------
__device__ float g_xp[(size_t)SEQ * BATCH * DIM];
__device__ __nv_bfloat16 g_hh[2][BATCH * DIM];
__device__ __nv_bfloat16 g_hl[2][BATCH * DIM];
__device__ __align__(16) unsigned short g_xhi[(size_t)SEQ * BATCH * DIM];
__device__ __align__(16) unsigned short g_xlo[(size_t)SEQ * BATCH * DIM];
__device__ __align__(16) unsigned short g_wthi[DIM * DIM];   // WxT [n][k]
__device__ __align__(16) unsigned short g_wtlo[DIM * DIM];
__device__ unsigned g_arr[4][32 * 8];    // [group][nstrip*8] padded flags
__device__ unsigned g_rel[4 * 32];       // [group*32]

// ---------------------------------------------------------------------------
// Helpers
// ---------------------------------------------------------------------------
__device__ __forceinline__ void split2(float v, unsigned short& hi, unsigned short& lo) {
    __nv_bfloat16 h = __float2bfloat16(v);
    __nv_bfloat16 l = __float2bfloat16(v - __bfloat162float(h));
    hi = __bfloat16_as_ushort(h);
    lo = __bfloat16_as_ushort(l);
}
__device__ __forceinline__ unsigned pck(unsigned short a, unsigned short b) {
    return ((unsigned)b << 16) | (unsigned)a;
}
__device__ __forceinline__ uint32_t smem_u32(const void* p) {
    uint32_t a;
    asm("{ .reg .u64 t; cvta.to.shared.u64 t, %1; cvt.u32.u64 %0, t; }"
        : "=r"(a) : "l"(p));
    return a;
}
__device__ __forceinline__ void mma_bf16(float c[4],
                                         unsigned a0, unsigned a1, unsigned a2, unsigned a3,
                                         unsigned b0, unsigned b1) {
    asm volatile(
        "mma.sync.aligned.m16n8k16.row.col.f32.bf16.bf16.f32 "
        "{%0,%1,%2,%3}, {%4,%5,%6,%7}, {%8,%9}, {%0,%1,%2,%3};"
        : "+f"(c[0]), "+f"(c[1]), "+f"(c[2]), "+f"(c[3])
        : "r"(a0), "r"(a1), "r"(a2), "r"(a3), "r"(b0), "r"(b1));
}
__device__ __forceinline__ void ldsm4(unsigned& r0, unsigned& r1, unsigned& r2, unsigned& r3,
                                      uint32_t addr) {
    asm volatile("ldmatrix.sync.aligned.m8n8.x4.shared.b16 {%0,%1,%2,%3}, [%4];"
                 : "=r"(r0), "=r"(r1), "=r"(r2), "=r"(r3) : "r"(addr));
}
__device__ __forceinline__ void cp16(uint32_t dst, const void* src) {
    asm volatile("cp.async.cg.shared.global [%0], [%1], 16;" :: "r"(dst), "l"(src));
}
#define CP_COMMIT() asm volatile("cp.async.commit_group;" ::: "memory")
#define CP_WAIT(n)  asm volatile("cp.async.wait_group %0;" :: "n"(n) : "memory")

__device__ __forceinline__ void st_rel(unsigned* p, unsigned v) {
    asm volatile("st.release.gpu.global.u32 [%0], %1;" :: "l"(p), "r"(v) : "memory");
}
__device__ __forceinline__ unsigned ld_acq(const unsigned* p) {
    unsigned v;
    asm volatile("ld.acquire.gpu.global.u32 %0, [%1];" : "=r"(v) : "l"(p) : "memory");
    return v;
}

// ---------------------------------------------------------------------------
// Split kernels
// ---------------------------------------------------------------------------
__global__ __launch_bounds__(256) void split_x_kernel(const float* __restrict__ src) {
    const size_t N = (size_t)SEQ * BATCH * DIM;
    for (size_t i = ((size_t)blockIdx.x * 256 + threadIdx.x) * 8; i < N;
         i += (size_t)gridDim.x * 256 * 8) {
        float4 v0 = *reinterpret_cast<const float4*>(src + i);
        float4 v1 = *reinterpret_cast<const float4*>(src + i + 4);
        unsigned short h[8], l[8];
        split2(v0.x, h[0], l[0]); split2(v0.y, h[1], l[1]);
        split2(v0.z, h[2], l[2]); split2(v0.w, h[3], l[3]);
        split2(v1.x, h[4], l[4]); split2(v1.y, h[5], l[5]);
        split2(v1.z, h[6], l[6]); split2(v1.w, h[7], l[7]);
        uint4 ph = { pck(h[0],h[1]), pck(h[2],h[3]), pck(h[4],h[5]), pck(h[6],h[7]) };
        uint4 pl = { pck(l[0],l[1]), pck(l[2],l[3]), pck(l[4],l[5]), pck(l[6],l[7]) };
        *reinterpret_cast<uint4*>(&g_xhi[i]) = ph;
        *reinterpret_cast<uint4*>(&g_xlo[i]) = pl;
    }
}

// Wx [k][n] -> transposed split [n][k]
__global__ __launch_bounds__(256) void split_wt_kernel(const float* __restrict__ W) {
    __shared__ unsigned short shi[32][33], slo[32][33];
    const int k0 = blockIdx.x * 32, n0 = blockIdx.y * 32;
    const int tid = threadIdx.x;
    #pragma unroll
    for (int j = 0; j < 4; j++) {
        const int idx = tid + j * 256;
        const int kk = idx >> 5, nn = idx & 31;
        float v = W[(size_t)(k0 + kk) * DIM + n0 + nn];
        unsigned short h, l;
        split2(v, h, l);
        shi[nn][kk] = h; slo[nn][kk] = l;
    }
    __syncthreads();
    #pragma unroll
    for (int j = 0; j < 4; j++) {
        const int idx = tid + j * 256;
        const int nn = idx >> 5, kk = idx & 31;
        g_wthi[(size_t)(n0 + nn) * DIM + k0 + kk] = shi[nn][kk];
        g_wtlo[(size_t)(n0 + nn) * DIM + k0 + kk] = slo[nn][kk];
    }
}

// ---------------------------------------------------------------------------
// Kernel 1: xp = X @ Wx + b, pure-bf16 double-buffered
// Dynamic smem: 2 stages x { Ahi, Alo, Bhi, Blo : ushort[64][72] } = 73728 B
// ---------------------------------------------------------------------------
#define STG_BYTES 36864
#define T72(p, r, c) ((p) + (r) * 72 + (c))

__global__ __launch_bounds__(256) void gemm_xp_mma(const float* __restrict__ bias)
{
    extern __shared__ char sg[];
    const uint32_t sbase = smem_u32(sg);

    const int tid = threadIdx.x, lane = tid & 31, wid = tid >> 5;
    const int m0 = blockIdx.y * 64, n0 = blockIdx.x * 64;
    const int g = lane >> 2, t4 = lane & 3;
    const int mt = wid >> 1;
    const int nh = wid & 1;

    const int lrow = tid >> 2;            // 0..63
    const int lcb  = (tid & 3) * 16;      // 0,16,32,48

    // per-thread cp.async sources / dests (A row = m0+lrow, B row = n0+lrow)
    const unsigned short* asrc_h = &g_xhi[(size_t)(m0 + lrow) * DIM + lcb];
    const unsigned short* asrc_l = &g_xlo[(size_t)(m0 + lrow) * DIM + lcb];
    const unsigned short* bsrc_h = &g_wthi[(size_t)(n0 + lrow) * DIM + lcb];
    const unsigned short* bsrc_l = &g_wtlo[(size_t)(n0 + lrow) * DIM + lcb];
    const uint32_t drow = (uint32_t)(lrow * 72 + lcb) * 2;

    float acc[4][4] = {};

    // issue loads for stage s, k offset k0
    auto issue = [&](int s, int k0) {
        const uint32_t b = sbase + s * STG_BYTES + drow;
        cp16(b,                 asrc_h + k0);
        cp16(b + 16,            asrc_h + k0 + 8);
        cp16(b +  9216,         asrc_l + k0);
        cp16(b +  9216 + 16,    asrc_l + k0 + 8);
        cp16(b + 18432,         bsrc_h + k0);
        cp16(b + 18432 + 16,    bsrc_h + k0 + 8);
        cp16(b + 27648,         bsrc_l + k0);
        cp16(b + 27648 + 16,    bsrc_l + k0 + 8);
    };

    issue(0, 0);
    CP_COMMIT();

    for (int kk = 0; kk < 16; kk++) {
        const int s = kk & 1;
        if (kk < 15) {
            issue(s ^ 1, (kk + 1) * 64);
            CP_COMMIT();
            CP_WAIT(1);
        } else {
            CP_WAIT(0);
        }
        __syncthreads();

        const unsigned short* Ahi = reinterpret_cast<const unsigned short*>(sg + s * STG_BYTES);
        const unsigned short* Alo = Ahi + 4608;
        const unsigned short* Bhi = Ahi + 9216;
        const unsigned short* Blo = Ahi + 13824;

        #pragma unroll
        for (int ks = 0; ks < 4; ks++) {
            const int ka = ks * 16 + 2 * t4;
            const int ar0 = mt * 16 + g, ar1 = ar0 + 8;
            unsigned ah0 = *(const unsigned*)T72(Ahi, ar0, ka);
            unsigned ah1 = *(const unsigned*)T72(Ahi, ar1, ka);
            unsigned ah2 = *(const unsigned*)T72(Ahi, ar0, ka + 8);
            unsigned ah3 = *(const unsigned*)T72(Ahi, ar1, ka + 8);
            unsigned al0 = *(const unsigned*)T72(Alo, ar0, ka);
            unsigned al1 = *(const unsigned*)T72(Alo, ar1, ka);
            unsigned al2 = *(const unsigned*)T72(Alo, ar0, ka + 8);
            unsigned al3 = *(const unsigned*)T72(Alo, ar1, ka + 8);
            #pragma unroll
            for (int nt = 0; nt < 4; nt++) {
                const int n = nh * 32 + nt * 8 + g;
                unsigned bh0 = *(const unsigned*)T72(Bhi, n, ka);
                unsigned bh1 = *(const unsigned*)T72(Bhi, n, ka + 8);
                unsigned bl0 = *(const unsigned*)T72(Blo, n, ka);
                unsigned bl1 = *(const unsigned*)T72(Blo, n, ka + 8);
                mma_bf16(acc[nt], ah0, ah1, ah2, ah3, bh0, bh1);
                mma_bf16(acc[nt], ah0, ah1, ah2, ah3, bl0, bl1);
                mma_bf16(acc[nt], al0, al1, al2, al3, bh0, bh1);
            }
        }
        __syncthreads();
    }

    #pragma unroll
    for (int nt = 0; nt < 4; nt++) {
        const int col = n0 + nh * 32 + nt * 8 + 2 * t4;
        const int r0 = m0 + mt * 16 + g;
        float2 bb = *reinterpret_cast<const float2*>(&bias[col]);
        float2 v0 = { acc[nt][0] + bb.x, acc[nt][1] + bb.y };
        float2 v1 = { acc[nt][2] + bb.x, acc[nt][3] + bb.y };
        *reinterpret_cast<float2*>(&g_xp[(size_t)r0 * DIM + col]) = v0;
        *reinterpret_cast<float2*>(&g_xp[(size_t)(r0 + 8) * DIM + col]) = v1;
    }
}

// ---------------------------------------------------------------------------
// Kernel 2: persistent recurrence, 4 independent 32-CTA groups
// ---------------------------------------------------------------------------
__global__ __launch_bounds__(THREADS_R, 1) void rnn_rec_kernel(
    const float* __restrict__ h0,
    const float* __restrict__ Wh,
    float* __restrict__ out)
{
    extern __shared__ char s_dyn[];
    uint2* whp_hi = reinterpret_cast<uint2*>(s_dyn);
    uint2* whp_lo = whp_hi + 8192;
    __nv_bfloat16* s_a = reinterpret_cast<__nv_bfloat16*>(s_dyn + WHP_BYTES);
    const uint32_t s_a_u32 = smem_u32(s_a);

    const int tid = threadIdx.x, lane = tid & 31, wid = tid >> 5;
    const int g = lane >> 2, t4 = lane & 3;
    const int mblk = blockIdx.x >> 5;        // group 0..3
    const int nstrip = blockIdx.x & 31;
    const int m0 = mblk * 32, n0 = nstrip * 32;
    const int mt = wid >> 2;
    const int nt = wid & 3;

    // ---- pack Wh strip into fragment order (once) ----
    for (int idx = tid; idx < 8192; idx += THREADS_R) {
        const int ks = idx >> 7;
        const int nti = (idx >> 5) & 3;
        const int ln = idx & 31;
        const int gg = ln >> 2, tt = ln & 3;
        const int n = n0 + nti * 8 + gg;
        const int kb = ks * 16 + 2 * tt;
        float w00 = __ldg(&Wh[(size_t)(kb + 0) * DIM + n]);
        float w01 = __ldg(&Wh[(size_t)(kb + 1) * DIM + n]);
        float w10 = __ldg(&Wh[(size_t)(kb + 8) * DIM + n]);
        float w11 = __ldg(&Wh[(size_t)(kb + 9) * DIM + n]);
        unsigned short h00, l00, h01, l01, h10, l10, h11, l11;
        split2(w00, h00, l00); split2(w01, h01, l01);
        split2(w10, h10, l10); split2(w11, h11, l11);
        whp_hi[idx] = make_uint2(pck(h00, h01), pck(h10, h11));
        whp_lo[idx] = make_uint2(pck(l00, l01), pck(l10, l11));
    }

    // ---- initial H rows of this group only ----
    for (int i = nstrip * THREADS_R + tid; i < 32 * DIM; i += 32 * THREADS_R) {
        const int r = i >> 10, c = i & (DIM - 1);
        unsigned short hi, lo;
        split2(h0[(size_t)(m0 + r) * DIM + c], hi, lo);
        g_hh[0][(size_t)(m0 + r) * DIM + c] = __ushort_as_bfloat16(hi);
        g_hl[0][(size_t)(m0 + r) * DIM + c] = __ushort_as_bfloat16(lo);
    }

    // ---- group barrier (32 CTAs sharing mblk) ----
    unsigned ep = 0;
    auto gbar = [&](unsigned e) {
        __syncthreads();
        if (nstrip == 0) {
            if (tid >= 1 && tid < 32) {
                while (ld_acq(&g_arr[mblk][tid * 8]) < e) { }
            }
            __syncthreads();
            if (tid == 0) st_rel(&g_rel[mblk * 32], e);
        } else {
            if (tid == 0) {
                st_rel(&g_arr[mblk][nstrip * 8], e);
                while (ld_acq(&g_rel[mblk * 32]) < e) { }
            }
        }
        __syncthreads();
    };
    gbar(++ep);

    const int r0 = m0 + mt * 16 + g;
    const int col = n0 + nt * 8 + 2 * t4;

    const int arow = mt * 16 + (lane & 15);
    const int acol = (lane >> 4) * 8;
    const uint32_t a_lane_off = (uint32_t)(arow * SROW + acol) * 2;

    const uint2* bh_ptr = whp_hi + nt * 32 + lane;
    const uint2* bl_ptr = whp_lo + nt * 32 + lane;

    for (int t = 0; t < SEQ; t++) {
        const int rb = t & 1, wb = rb ^ 1;
        const __nv_bfloat16* Hh = g_hh[rb];
        const __nv_bfloat16* Hl = g_hl[rb];

        // prefetch xp for this step (independent of H)
        const size_t ob0 = ((size_t)t * BATCH + r0) * DIM + col;
        const size_t ob1 = ((size_t)t * BATCH + r0 + 8) * DIM + col;
        float2 x0 = __ldg(reinterpret_cast<const float2*>(&g_xp[ob0]));
        float2 x1 = __ldg(reinterpret_cast<const float2*>(&g_xp[ob1]));

        float c[4] = {0.f, 0.f, 0.f, 0.f};

        // stage chunk 0
        {
            #pragma unroll
            for (int i = 0; i < 8; i++) {
                const int idx = tid + i * THREADS_R;
                const int half = idx >> 10;
                const int rem = idx & 1023;
                const int row = rem >> 5, seg = rem & 31;
                const __nv_bfloat16* src =
                    (half ? Hl : Hh) + (size_t)(m0 + row) * DIM + seg * 8;
                const uint32_t dst = s_a_u32 +
                    (uint32_t)(half * AHALF + row * SROW + seg * 8) * 2;
                cp16(dst, src);
            }
            CP_COMMIT();
        }

        #pragma unroll
        for (int ch = 0; ch < NCH; ch++) {
            const int slot = ch & 1;
            if (ch + 1 < NCH) {
                const int nslot = slot ^ 1;
                const int k0 = (ch + 1) * CHUNK;
                #pragma unroll
                for (int i = 0; i < 8; i++) {
                    const int idx = tid + i * THREADS_R;
                    const int half = idx >> 10;
                    const int rem = idx & 1023;
                    const int row = rem >> 5, seg = rem & 31;
                    const __nv_bfloat16* src =
                        (half ? Hl : Hh) + (size_t)(m0 + row) * DIM + k0 + seg * 8;
                    const uint32_t dst = s_a_u32 +
                        (uint32_t)(nslot * ASLOT + half * AHALF + row * SROW + seg * 8) * 2;
                    cp16(dst, src);
                }
                CP_COMMIT();
                CP_WAIT(1);
            } else {
                CP_WAIT(0);
            }
            __syncthreads();

            const uint32_t a_hi_base = s_a_u32 + (uint32_t)(slot * ASLOT) * 2 + a_lane_off;
            const uint32_t a_lo_base = a_hi_base + (uint32_t)AHALF * 2;

            #pragma unroll
            for (int ks = 0; ks < CHUNK / 16; ks++) {
                unsigned ah0, ah1, ah2, ah3, al0, al1, al2, al3;
                ldsm4(ah0, ah1, ah2, ah3, a_hi_base + ks * 32);
                ldsm4(al0, al1, al2, al3, a_lo_base + ks * 32);
                const int ksg = ch * (CHUNK / 16) + ks;
                uint2 bh = bh_ptr[ksg * 128];
                uint2 bl = bl_ptr[ksg * 128];
                mma_bf16(c, ah0, ah1, ah2, ah3, bh.x, bh.y);
                mma_bf16(c, ah0, ah1, ah2, ah3, bl.x, bl.y);
                mma_bf16(c, al0, al1, al2, al3, bh.x, bh.y);
            }
            __syncthreads();
        }

        // epilogue
        {
            float v0 = tanhf(c[0] + x0.x), v1 = tanhf(c[1] + x0.y);
            float v2 = tanhf(c[2] + x1.x), v3 = tanhf(c[3] + x1.y);
            float2 o0 = {v0, v1}, o1 = {v2, v3};
            *reinterpret_cast<float2*>(&out[ob0]) = o0;
            *reinterpret_cast<float2*>(&out[ob1]) = o1;
            unsigned short hs0, ls0, hs1, ls1;
            unsigned* HHn = reinterpret_cast<unsigned*>(g_hh[wb]);
            unsigned* HLn = reinterpret_cast<unsigned*>(g_hl[wb]);
            const int ci = col >> 1;
            split2(v0, hs0, ls0); split2(v1, hs1, ls1);
            HHn[(size_t)r0 * KD2 + ci] = pck(hs0, hs1);
            HLn[(size_t)r0 * KD2 + ci] = pck(ls0, ls1);
            split2(v2, hs0, ls0); split2(v3, hs1, ls1);
            HHn[(size_t)(r0 + 8) * KD2 + ci] = pck(hs0, hs1);
            HLn[(size_t)(r0 + 8) * KD2 + ci] = pck(ls0, ls1);
        }
        gbar(++ep);
    }
}

// ---------------------------------------------------------------------------
// Launcher: inputs: x, h0, Wx, Wh, b
// ---------------------------------------------------------------------------
extern "C" void kernel_launch(void* const* d_in, const int* in_sizes, int n_in,
                              void* d_out, int out_size)
{
    const float* x  = (const float*)d_in[0];
    const float* h0 = (const float*)d_in[1];
    const float* Wx = (const float*)d_in[2];
    const float* Wh = (const float*)d_in[3];
    const float* b  = (const float*)d_in[4];
    float* out = (float*)d_out;

    cudaFuncSetAttribute(rnn_rec_kernel,
                         cudaFuncAttributeMaxDynamicSharedMemorySize, DYN_BYTES);
    cudaFuncSetAttribute(gemm_xp_mma,
                         cudaFuncAttributeMaxDynamicSharedMemorySize, 2 * STG_BYTES);

    void* a0 = nullptr; void* a1 = nullptr;
    cudaGetSymbolAddress(&a0, g_arr);
    cudaGetSymbolAddress(&a1, g_rel);
    cudaMemsetAsync(a0, 0, sizeof(unsigned) * 4 * 32 * 8);
    cudaMemsetAsync(a1, 0, sizeof(unsigned) * 4 * 32);

    // 0) precompute bf16 splits
    split_x_kernel<<<2048, 256>>>(x);
    {
        dim3 grid(DIM / 32, DIM / 32);
        split_wt_kernel<<<grid, 256>>>(Wx);
    }
    // 1) xp = x @ Wx + b
    {
        dim3 grid(DIM / 64, (SEQ * BATCH) / 64);
        gemm_xp_mma<<<grid, 256, 2 * STG_BYTES>>>(b);
    }
    // 2) persistent recurrence
    rnn_rec_kernel<<<GRID_R, THREADS_R, DYN_BYTES>>>(h0, Wh, out);
}

// round 11
// speedup vs baseline: 3.4889x; 1.0300x over previous
#include <cuda_runtime.h>
#include <cuda_bf16.h>
#include <math.h>
#include <stdint.h>

#define SEQ 128
#define BATCH 128
#define DIM 1024
#define KD2 (DIM / 2)

#define GRID_R 128
#define THREADS_R 256

#define CHUNK 256
#define NCH (DIM / CHUNK)
#define SROW 264
#define AHALF (32 * SROW)
#define ASLOT (2 * AHALF)
#define WHP_BYTES 131072
#define DYN_BYTES (WHP_BYTES + 2 * ASLOT * 2)

// ---------------------------------------------------------------------------
// Global scratch
// ---------------------------------------------------------------------------
__device__ float g_xp[(size_t)SEQ * BATCH * DIM];
__device__ __nv_bfloat16 g_hh[2][BATCH * DIM];
__device__ __nv_bfloat16 g_hl[2][BATCH * DIM];
__device__ __align__(16) unsigned short g_xhi[(size_t)SEQ * BATCH * DIM];
__device__ __align__(16) unsigned short g_xlo[(size_t)SEQ * BATCH * DIM];
__device__ __align__(16) unsigned short g_wthi[DIM * DIM];   // WxT [n][k]
__device__ __align__(16) unsigned short g_wtlo[DIM * DIM];
__device__ unsigned g_flag[4][32 * 16];   // [group][strip*16] publication counters

// ---------------------------------------------------------------------------
// Helpers
// ---------------------------------------------------------------------------
__device__ __forceinline__ void split2(float v, unsigned short& hi, unsigned short& lo) {
    __nv_bfloat16 h = __float2bfloat16(v);
    __nv_bfloat16 l = __float2bfloat16(v - __bfloat162float(h));
    hi = __bfloat16_as_ushort(h);
    lo = __bfloat16_as_ushort(l);
}
__device__ __forceinline__ unsigned pck(unsigned short a, unsigned short b) {
    return ((unsigned)b << 16) | (unsigned)a;
}
__device__ __forceinline__ uint32_t smem_u32(const void* p) {
    uint32_t a;
    asm("{ .reg .u64 t; cvta.to.shared.u64 t, %1; cvt.u32.u64 %0, t; }"
        : "=r"(a) : "l"(p));
    return a;
}
__device__ __forceinline__ void mma_bf16(float c[4],
                                         unsigned a0, unsigned a1, unsigned a2, unsigned a3,
                                         unsigned b0, unsigned b1) {
    asm volatile(
        "mma.sync.aligned.m16n8k16.row.col.f32.bf16.bf16.f32 "
        "{%0,%1,%2,%3}, {%4,%5,%6,%7}, {%8,%9}, {%0,%1,%2,%3};"
        : "+f"(c[0]), "+f"(c[1]), "+f"(c[2]), "+f"(c[3])
        : "r"(a0), "r"(a1), "r"(a2), "r"(a3), "r"(b0), "r"(b1));
}
__device__ __forceinline__ void ldsm4(unsigned& r0, unsigned& r1, unsigned& r2, unsigned& r3,
                                      uint32_t addr) {
    asm volatile("ldmatrix.sync.aligned.m8n8.x4.shared.b16 {%0,%1,%2,%3}, [%4];"
                 : "=r"(r0), "=r"(r1), "=r"(r2), "=r"(r3) : "r"(addr));
}
__device__ __forceinline__ void cp16(uint32_t dst, const void* src) {
    asm volatile("cp.async.cg.shared.global [%0], [%1], 16;" :: "r"(dst), "l"(src));
}
#define CP_COMMIT() asm volatile("cp.async.commit_group;" ::: "memory")
#define CP_WAIT(n)  asm volatile("cp.async.wait_group %0;" :: "n"(n) : "memory")

__device__ __forceinline__ void st_rel(unsigned* p, unsigned v) {
    asm volatile("st.release.gpu.global.u32 [%0], %1;" :: "l"(p), "r"(v) : "memory");
}
__device__ __forceinline__ unsigned ld_acq(const unsigned* p) {
    unsigned v;
    asm volatile("ld.acquire.gpu.global.u32 %0, [%1];" : "=r"(v) : "l"(p) : "memory");
    return v;
}

// ---------------------------------------------------------------------------
// Split kernels
// ---------------------------------------------------------------------------
__global__ __launch_bounds__(256) void split_x_kernel(const float* __restrict__ src) {
    const size_t N = (size_t)SEQ * BATCH * DIM;
    for (size_t i = ((size_t)blockIdx.x * 256 + threadIdx.x) * 8; i < N;
         i += (size_t)gridDim.x * 256 * 8) {
        float4 v0 = *reinterpret_cast<const float4*>(src + i);
        float4 v1 = *reinterpret_cast<const float4*>(src + i + 4);
        unsigned short h[8], l[8];
        split2(v0.x, h[0], l[0]); split2(v0.y, h[1], l[1]);
        split2(v0.z, h[2], l[2]); split2(v0.w, h[3], l[3]);
        split2(v1.x, h[4], l[4]); split2(v1.y, h[5], l[5]);
        split2(v1.z, h[6], l[6]); split2(v1.w, h[7], l[7]);
        uint4 ph = { pck(h[0],h[1]), pck(h[2],h[3]), pck(h[4],h[5]), pck(h[6],h[7]) };
        uint4 pl = { pck(l[0],l[1]), pck(l[2],l[3]), pck(l[4],l[5]), pck(l[6],l[7]) };
        *reinterpret_cast<uint4*>(&g_xhi[i]) = ph;
        *reinterpret_cast<uint4*>(&g_xlo[i]) = pl;
    }
}

__global__ __launch_bounds__(256) void split_wt_kernel(const float* __restrict__ W) {
    __shared__ unsigned short shi[32][33], slo[32][33];
    const int k0 = blockIdx.x * 32, n0 = blockIdx.y * 32;
    const int tid = threadIdx.x;
    #pragma unroll
    for (int j = 0; j < 4; j++) {
        const int idx = tid + j * 256;
        const int kk = idx >> 5, nn = idx & 31;
        float v = W[(size_t)(k0 + kk) * DIM + n0 + nn];
        unsigned short h, l;
        split2(v, h, l);
        shi[nn][kk] = h; slo[nn][kk] = l;
    }
    __syncthreads();
    #pragma unroll
    for (int j = 0; j < 4; j++) {
        const int idx = tid + j * 256;
        const int nn = idx >> 5, kk = idx & 31;
        g_wthi[(size_t)(n0 + nn) * DIM + k0 + kk] = shi[nn][kk];
        g_wtlo[(size_t)(n0 + nn) * DIM + k0 + kk] = slo[nn][kk];
    }
}

// ---------------------------------------------------------------------------
// Kernel 1: xp = X @ Wx + b, pure-bf16 double-buffered (unchanged)
// ---------------------------------------------------------------------------
#define STG_BYTES 36864
#define T72(p, r, c) ((p) + (r) * 72 + (c))

__global__ __launch_bounds__(256) void gemm_xp_mma(const float* __restrict__ bias)
{
    extern __shared__ char sg[];
    const uint32_t sbase = smem_u32(sg);

    const int tid = threadIdx.x, lane = tid & 31, wid = tid >> 5;
    const int m0 = blockIdx.y * 64, n0 = blockIdx.x * 64;
    const int g = lane >> 2, t4 = lane & 3;
    const int mt = wid >> 1;
    const int nh = wid & 1;

    const int lrow = tid >> 2;
    const int lcb  = (tid & 3) * 16;

    const unsigned short* asrc_h = &g_xhi[(size_t)(m0 + lrow) * DIM + lcb];
    const unsigned short* asrc_l = &g_xlo[(size_t)(m0 + lrow) * DIM + lcb];
    const unsigned short* bsrc_h = &g_wthi[(size_t)(n0 + lrow) * DIM + lcb];
    const unsigned short* bsrc_l = &g_wtlo[(size_t)(n0 + lrow) * DIM + lcb];
    const uint32_t drow = (uint32_t)(lrow * 72 + lcb) * 2;

    float acc[4][4] = {};

    auto issue = [&](int s, int k0) {
        const uint32_t b = sbase + s * STG_BYTES + drow;
        cp16(b,                 asrc_h + k0);
        cp16(b + 16,            asrc_h + k0 + 8);
        cp16(b +  9216,         asrc_l + k0);
        cp16(b +  9216 + 16,    asrc_l + k0 + 8);
        cp16(b + 18432,         bsrc_h + k0);
        cp16(b + 18432 + 16,    bsrc_h + k0 + 8);
        cp16(b + 27648,         bsrc_l + k0);
        cp16(b + 27648 + 16,    bsrc_l + k0 + 8);
    };

    issue(0, 0);
    CP_COMMIT();

    for (int kk = 0; kk < 16; kk++) {
        const int s = kk & 1;
        if (kk < 15) {
            issue(s ^ 1, (kk + 1) * 64);
            CP_COMMIT();
            CP_WAIT(1);
        } else {
            CP_WAIT(0);
        }
        __syncthreads();

        const unsigned short* Ahi = reinterpret_cast<const unsigned short*>(sg + s * STG_BYTES);
        const unsigned short* Alo = Ahi + 4608;
        const unsigned short* Bhi = Ahi + 9216;
        const unsigned short* Blo = Ahi + 13824;

        #pragma unroll
        for (int ks = 0; ks < 4; ks++) {
            const int ka = ks * 16 + 2 * t4;
            const int ar0 = mt * 16 + g, ar1 = ar0 + 8;
            unsigned ah0 = *(const unsigned*)T72(Ahi, ar0, ka);
            unsigned ah1 = *(const unsigned*)T72(Ahi, ar1, ka);
            unsigned ah2 = *(const unsigned*)T72(Ahi, ar0, ka + 8);
            unsigned ah3 = *(const unsigned*)T72(Ahi, ar1, ka + 8);
            unsigned al0 = *(const unsigned*)T72(Alo, ar0, ka);
            unsigned al1 = *(const unsigned*)T72(Alo, ar1, ka);
            unsigned al2 = *(const unsigned*)T72(Alo, ar0, ka + 8);
            unsigned al3 = *(const unsigned*)T72(Alo, ar1, ka + 8);
            #pragma unroll
            for (int nt = 0; nt < 4; nt++) {
                const int n = nh * 32 + nt * 8 + g;
                unsigned bh0 = *(const unsigned*)T72(Bhi, n, ka);
                unsigned bh1 = *(const unsigned*)T72(Bhi, n, ka + 8);
                unsigned bl0 = *(const unsigned*)T72(Blo, n, ka);
                unsigned bl1 = *(const unsigned*)T72(Blo, n, ka + 8);
                mma_bf16(acc[nt], ah0, ah1, ah2, ah3, bh0, bh1);
                mma_bf16(acc[nt], ah0, ah1, ah2, ah3, bl0, bl1);
                mma_bf16(acc[nt], al0, al1, al2, al3, bh0, bh1);
            }
        }
        __syncthreads();
    }

    #pragma unroll
    for (int nt = 0; nt < 4; nt++) {
        const int col = n0 + nh * 32 + nt * 8 + 2 * t4;
        const int r0 = m0 + mt * 16 + g;
        float2 bb = *reinterpret_cast<const float2*>(&bias[col]);
        float2 v0 = { acc[nt][0] + bb.x, acc[nt][1] + bb.y };
        float2 v1 = { acc[nt][2] + bb.x, acc[nt][3] + bb.y };
        *reinterpret_cast<float2*>(&g_xp[(size_t)r0 * DIM + col]) = v0;
        *reinterpret_cast<float2*>(&g_xp[(size_t)(r0 + 8) * DIM + col]) = v1;
    }
}

// ---------------------------------------------------------------------------
// Kernel 2: persistent recurrence, per-strip dataflow flags (no barrier)
// ---------------------------------------------------------------------------
__global__ __launch_bounds__(THREADS_R, 1) void rnn_rec_kernel(
    const float* __restrict__ h0,
    const float* __restrict__ Wh,
    float* __restrict__ out)
{
    extern __shared__ char s_dyn[];
    uint4* whp = reinterpret_cast<uint4*>(s_dyn);          // [(ks*4+nt)*32+lane] {bh.x,bh.y,bl.x,bl.y}
    __nv_bfloat16* s_a = reinterpret_cast<__nv_bfloat16*>(s_dyn + WHP_BYTES);
    const uint32_t s_a_u32 = smem_u32(s_a);

    const int tid = threadIdx.x, lane = tid & 31, wid = tid >> 5;
    const int g = lane >> 2, t4 = lane & 3;
    const int mblk = blockIdx.x >> 5;        // group 0..3
    const int nstrip = blockIdx.x & 31;
    const int m0 = mblk * 32, n0 = nstrip * 32;
    const int mt = wid >> 2;
    const int nt = wid & 3;

    // ---- pack Wh strip into fused hi/lo fragment order (once) ----
    for (int idx = tid; idx < 8192; idx += THREADS_R) {
        const int ks = idx >> 7;
        const int nti = (idx >> 5) & 3;
        const int ln = idx & 31;
        const int gg = ln >> 2, tt = ln & 3;
        const int n = n0 + nti * 8 + gg;
        const int kb = ks * 16 + 2 * tt;
        float w00 = __ldg(&Wh[(size_t)(kb + 0) * DIM + n]);
        float w01 = __ldg(&Wh[(size_t)(kb + 1) * DIM + n]);
        float w10 = __ldg(&Wh[(size_t)(kb + 8) * DIM + n]);
        float w11 = __ldg(&Wh[(size_t)(kb + 9) * DIM + n]);
        unsigned short h00, l00, h01, l01, h10, l10, h11, l11;
        split2(w00, h00, l00); split2(w01, h01, l01);
        split2(w10, h10, l10); split2(w11, h11, l11);
        whp[idx] = make_uint4(pck(h00, h01), pck(h10, h11),
                              pck(l00, l01), pck(l10, l11));
    }

    // ---- init: write OWN strip of H0, then publish flag = 1 ----
    for (int i = tid; i < 32 * 32; i += THREADS_R) {
        const int r = i >> 5, cc = i & 31;
        unsigned short hi, lo;
        split2(h0[(size_t)(m0 + r) * DIM + n0 + cc], hi, lo);
        g_hh[0][(size_t)(m0 + r) * DIM + n0 + cc] = __ushort_as_bfloat16(hi);
        g_hl[0][(size_t)(m0 + r) * DIM + n0 + cc] = __ushort_as_bfloat16(lo);
    }
    __syncthreads();
    if (tid == 0) st_rel(&g_flag[mblk][nstrip * 16], 1u);

    const int r0 = m0 + mt * 16 + g;
    const int col = n0 + nt * 8 + 2 * t4;

    const int arow = mt * 16 + (lane & 15);
    const int acol = (lane >> 4) * 8;
    const uint32_t a_lane_off = (uint32_t)(arow * SROW + acol) * 2;

    const uint4* bp = whp + nt * 32 + lane;

    // this thread's cp.async segment and its producer-strip flags
    const int seg = tid & 31;           // 8-col segment within each chunk
    const int s0 = seg >> 2;            // strip-in-chunk 0..7
    const unsigned* fp0 = &g_flag[mblk][(0 * 8 + s0) * 16];
    const unsigned* fp1 = &g_flag[mblk][(1 * 8 + s0) * 16];
    const unsigned* fp2 = &g_flag[mblk][(2 * 8 + s0) * 16];
    const unsigned* fp3 = &g_flag[mblk][(3 * 8 + s0) * 16];

    for (int t = 0; t < SEQ; t++) {
        const int rb = t & 1, wb = rb ^ 1;
        const __nv_bfloat16* Hh = g_hh[rb];
        const __nv_bfloat16* Hl = g_hl[rb];
        const unsigned tgt = (unsigned)(t + 1);

        // prefetch xp (independent of H)
        const size_t ob0 = ((size_t)t * BATCH + r0) * DIM + col;
        const size_t ob1 = ((size_t)t * BATCH + r0 + 8) * DIM + col;
        float2 x0 = __ldg(reinterpret_cast<const float2*>(&g_xp[ob0]));
        float2 x1 = __ldg(reinterpret_cast<const float2*>(&g_xp[ob1]));

        float c[4] = {0.f, 0.f, 0.f, 0.f};

        // per-thread cp.async issue for chunk ch into slot
        auto issueA = [&](int ch, int slot) {
            const int k0 = ch * CHUNK;
            #pragma unroll
            for (int i = 0; i < 8; i++) {
                const int idx = tid + i * THREADS_R;
                const int half = idx >> 10;
                const int row = (idx & 1023) >> 5;
                const __nv_bfloat16* src =
                    (half ? Hl : Hh) + (size_t)(m0 + row) * DIM + k0 + seg * 8;
                const uint32_t dst = s_a_u32 +
                    (uint32_t)(slot * ASLOT + half * AHALF + row * SROW + seg * 8) * 2;
                cp16(dst, src);
            }
        };

        // wait for chunk-0 producer strip, stage chunk 0 immediately
        while (ld_acq(fp0) < tgt) { }
        issueA(0, 0);
        CP_COMMIT();
        // wait for remaining strips while chunk 0 is in flight
        for (;;) {
            unsigned v1 = ld_acq(fp1), v2 = ld_acq(fp2), v3 = ld_acq(fp3);
            if (v1 >= tgt && v2 >= tgt && v3 >= tgt) break;
        }

        #pragma unroll
        for (int ch = 0; ch < NCH; ch++) {
            const int slot = ch & 1;
            if (ch + 1 < NCH) {
                issueA(ch + 1, slot ^ 1);
                CP_COMMIT();
                CP_WAIT(1);
            } else {
                CP_WAIT(0);
            }
            __syncthreads();

            const uint32_t a_hi_base = s_a_u32 + (uint32_t)(slot * ASLOT) * 2 + a_lane_off;
            const uint32_t a_lo_base = a_hi_base + (uint32_t)AHALF * 2;

            #pragma unroll
            for (int ks = 0; ks < CHUNK / 16; ks++) {
                unsigned ah0, ah1, ah2, ah3, al0, al1, al2, al3;
                ldsm4(ah0, ah1, ah2, ah3, a_hi_base + ks * 32);
                ldsm4(al0, al1, al2, al3, a_lo_base + ks * 32);
                const int ksg = ch * (CHUNK / 16) + ks;
                uint4 bb = bp[ksg * 128];
                mma_bf16(c, ah0, ah1, ah2, ah3, bb.x, bb.y);
                mma_bf16(c, ah0, ah1, ah2, ah3, bb.z, bb.w);
                mma_bf16(c, al0, al1, al2, al3, bb.x, bb.y);
            }
            __syncthreads();
        }

        // epilogue: tanh, publish next H FIRST, then write output
        {
            float v0 = tanhf(c[0] + x0.x), v1 = tanhf(c[1] + x0.y);
            float v2 = tanhf(c[2] + x1.x), v3 = tanhf(c[3] + x1.y);
            unsigned short hs0, ls0, hs1, ls1;
            unsigned* HHn = reinterpret_cast<unsigned*>(g_hh[wb]);
            unsigned* HLn = reinterpret_cast<unsigned*>(g_hl[wb]);
            const int ci = col >> 1;
            split2(v0, hs0, ls0); split2(v1, hs1, ls1);
            HHn[(size_t)r0 * KD2 + ci] = pck(hs0, hs1);
            HLn[(size_t)r0 * KD2 + ci] = pck(ls0, ls1);
            split2(v2, hs0, ls0); split2(v3, hs1, ls1);
            HHn[(size_t)(r0 + 8) * KD2 + ci] = pck(hs0, hs1);
            HLn[(size_t)(r0 + 8) * KD2 + ci] = pck(ls0, ls1);
            __syncthreads();
            if (tid == 0) st_rel(&g_flag[mblk][nstrip * 16], (unsigned)(t + 2));
            float2 o0 = {v0, v1}, o1 = {v2, v3};
            *reinterpret_cast<float2*>(&out[ob0]) = o0;
            *reinterpret_cast<float2*>(&out[ob1]) = o1;
        }
    }
}

// ---------------------------------------------------------------------------
// Launcher: inputs: x, h0, Wx, Wh, b
// ---------------------------------------------------------------------------
extern "C" void kernel_launch(void* const* d_in, const int* in_sizes, int n_in,
                              void* d_out, int out_size)
{
    const float* x  = (const float*)d_in[0];
    const float* h0 = (const float*)d_in[1];
    const float* Wx = (const float*)d_in[2];
    const float* Wh = (const float*)d_in[3];
    const float* b  = (const float*)d_in[4];
    float* out = (float*)d_out;

    cudaFuncSetAttribute(rnn_rec_kernel,
                         cudaFuncAttributeMaxDynamicSharedMemorySize, DYN_BYTES);
    cudaFuncSetAttribute(gemm_xp_mma,
                         cudaFuncAttributeMaxDynamicSharedMemorySize, 2 * STG_BYTES);

    void* f0 = nullptr;
    cudaGetSymbolAddress(&f0, g_flag);
    cudaMemsetAsync(f0, 0, sizeof(unsigned) * 4 * 32 * 16);

    split_x_kernel<<<2048, 256>>>(x);
    {
        dim3 grid(DIM / 32, DIM / 32);
        split_wt_kernel<<<grid, 256>>>(Wx);
    }
    {
        dim3 grid(DIM / 64, (SEQ * BATCH) / 64);
        gemm_xp_mma<<<grid, 256, 2 * STG_BYTES>>>(b);
    }
    rnn_rec_kernel<<<GRID_R, THREADS_R, DYN_BYTES>>>(h0, Wh, out);
}

// round 12
// speedup vs baseline: 4.5204x; 1.2957x over previous
#include <cuda_runtime.h>
#include <cuda_bf16.h>
#include <math.h>
#include <stdint.h>

#define SEQ 128
#define BATCH 128
#define DIM 1024
#define KD2 (DIM / 2)

#define GRID_R 128
#define THREADS_R 256

#define AROW 1032                 // padded A row stride (elements)
#define AHALF (32 * AROW)         // elements per half (hi or lo)
#define A_BYTES (2 * AHALF * 2)   // 132096
#define P_BYTES (8 * 32 * 36 * 4) // 36864 partial buffer
#define DYN_R (A_BYTES + P_BYTES)

// ---------------------------------------------------------------------------
// Global scratch
// ---------------------------------------------------------------------------
__device__ float g_xp[(size_t)SEQ * BATCH * DIM];
__device__ __nv_bfloat16 g_hh[2][BATCH * DIM];
__device__ __nv_bfloat16 g_hl[2][BATCH * DIM];
__device__ __align__(16) unsigned short g_xhi[(size_t)SEQ * BATCH * DIM];
__device__ __align__(16) unsigned short g_xlo[(size_t)SEQ * BATCH * DIM];
__device__ __align__(16) unsigned short g_wthi[DIM * DIM];
__device__ __align__(16) unsigned short g_wtlo[DIM * DIM];
__device__ unsigned g_flag[4][32 * 32];   // [group][strip*32] 128B-strided

// ---------------------------------------------------------------------------
// Helpers
// ---------------------------------------------------------------------------
__device__ __forceinline__ void split2(float v, unsigned short& hi, unsigned short& lo) {
    __nv_bfloat16 h = __float2bfloat16(v);
    __nv_bfloat16 l = __float2bfloat16(v - __bfloat162float(h));
    hi = __bfloat16_as_ushort(h);
    lo = __bfloat16_as_ushort(l);
}
__device__ __forceinline__ unsigned pck(unsigned short a, unsigned short b) {
    return ((unsigned)b << 16) | (unsigned)a;
}
__device__ __forceinline__ uint32_t smem_u32(const void* p) {
    uint32_t a;
    asm("{ .reg .u64 t; cvta.to.shared.u64 t, %1; cvt.u32.u64 %0, t; }"
        : "=r"(a) : "l"(p));
    return a;
}
__device__ __forceinline__ void mma_bf16(float c[4],
                                         unsigned a0, unsigned a1, unsigned a2, unsigned a3,
                                         unsigned b0, unsigned b1) {
    asm volatile(
        "mma.sync.aligned.m16n8k16.row.col.f32.bf16.bf16.f32 "
        "{%0,%1,%2,%3}, {%4,%5,%6,%7}, {%8,%9}, {%0,%1,%2,%3};"
        : "+f"(c[0]), "+f"(c[1]), "+f"(c[2]), "+f"(c[3])
        : "r"(a0), "r"(a1), "r"(a2), "r"(a3), "r"(b0), "r"(b1));
}
__device__ __forceinline__ void ldsm4(unsigned& r0, unsigned& r1, unsigned& r2, unsigned& r3,
                                      uint32_t addr) {
    asm volatile("ldmatrix.sync.aligned.m8n8.x4.shared.b16 {%0,%1,%2,%3}, [%4];"
                 : "=r"(r0), "=r"(r1), "=r"(r2), "=r"(r3) : "r"(addr));
}
__device__ __forceinline__ void cp16(uint32_t dst, const void* src) {
    asm volatile("cp.async.cg.shared.global [%0], [%1], 16;" :: "r"(dst), "l"(src));
}
#define CP_COMMIT() asm volatile("cp.async.commit_group;" ::: "memory")
#define CP_WAIT(n)  asm volatile("cp.async.wait_group %0;" :: "n"(n) : "memory")

__device__ __forceinline__ void st_rel(unsigned* p, unsigned v) {
    asm volatile("st.release.gpu.global.u32 [%0], %1;" :: "l"(p), "r"(v) : "memory");
}
__device__ __forceinline__ unsigned ld_acq(const unsigned* p) {
    unsigned v;
    asm volatile("ld.acquire.gpu.global.u32 %0, [%1];" : "=r"(v) : "l"(p) : "memory");
    return v;
}

// ---------------------------------------------------------------------------
// Split kernels (unchanged)
// ---------------------------------------------------------------------------
__global__ __launch_bounds__(256) void split_x_kernel(const float* __restrict__ src) {
    const size_t N = (size_t)SEQ * BATCH * DIM;
    for (size_t i = ((size_t)blockIdx.x * 256 + threadIdx.x) * 8; i < N;
         i += (size_t)gridDim.x * 256 * 8) {
        float4 v0 = *reinterpret_cast<const float4*>(src + i);
        float4 v1 = *reinterpret_cast<const float4*>(src + i + 4);
        unsigned short h[8], l[8];
        split2(v0.x, h[0], l[0]); split2(v0.y, h[1], l[1]);
        split2(v0.z, h[2], l[2]); split2(v0.w, h[3], l[3]);
        split2(v1.x, h[4], l[4]); split2(v1.y, h[5], l[5]);
        split2(v1.z, h[6], l[6]); split2(v1.w, h[7], l[7]);
        uint4 ph = { pck(h[0],h[1]), pck(h[2],h[3]), pck(h[4],h[5]), pck(h[6],h[7]) };
        uint4 pl = { pck(l[0],l[1]), pck(l[2],l[3]), pck(l[4],l[5]), pck(l[6],l[7]) };
        *reinterpret_cast<uint4*>(&g_xhi[i]) = ph;
        *reinterpret_cast<uint4*>(&g_xlo[i]) = pl;
    }
}

__global__ __launch_bounds__(256) void split_wt_kernel(const float* __restrict__ W) {
    __shared__ unsigned short shi[32][33], slo[32][33];
    const int k0 = blockIdx.x * 32, n0 = blockIdx.y * 32;
    const int tid = threadIdx.x;
    #pragma unroll
    for (int j = 0; j < 4; j++) {
        const int idx = tid + j * 256;
        const int kk = idx >> 5, nn = idx & 31;
        float v = W[(size_t)(k0 + kk) * DIM + n0 + nn];
        unsigned short h, l;
        split2(v, h, l);
        shi[nn][kk] = h; slo[nn][kk] = l;
    }
    __syncthreads();
    #pragma unroll
    for (int j = 0; j < 4; j++) {
        const int idx = tid + j * 256;
        const int nn = idx >> 5, kk = idx & 31;
        g_wthi[(size_t)(n0 + nn) * DIM + k0 + kk] = shi[nn][kk];
        g_wtlo[(size_t)(n0 + nn) * DIM + k0 + kk] = slo[nn][kk];
    }
}

// ---------------------------------------------------------------------------
// Kernel 1: xp = X @ Wx + b, pure-bf16 double-buffered (unchanged)
// ---------------------------------------------------------------------------
#define STG_BYTES 36864
#define T72(p, r, c) ((p) + (r) * 72 + (c))

__global__ __launch_bounds__(256) void gemm_xp_mma(const float* __restrict__ bias)
{
    extern __shared__ char sg[];
    const uint32_t sbase = smem_u32(sg);

    const int tid = threadIdx.x, lane = tid & 31, wid = tid >> 5;
    const int m0 = blockIdx.y * 64, n0 = blockIdx.x * 64;
    const int g = lane >> 2, t4 = lane & 3;
    const int mt = wid >> 1;
    const int nh = wid & 1;

    const int lrow = tid >> 2;
    const int lcb  = (tid & 3) * 16;

    const unsigned short* asrc_h = &g_xhi[(size_t)(m0 + lrow) * DIM + lcb];
    const unsigned short* asrc_l = &g_xlo[(size_t)(m0 + lrow) * DIM + lcb];
    const unsigned short* bsrc_h = &g_wthi[(size_t)(n0 + lrow) * DIM + lcb];
    const unsigned short* bsrc_l = &g_wtlo[(size_t)(n0 + lrow) * DIM + lcb];
    const uint32_t drow = (uint32_t)(lrow * 72 + lcb) * 2;

    float acc[4][4] = {};

    auto issue = [&](int s, int k0) {
        const uint32_t b = sbase + s * STG_BYTES + drow;
        cp16(b,                 asrc_h + k0);
        cp16(b + 16,            asrc_h + k0 + 8);
        cp16(b +  9216,         asrc_l + k0);
        cp16(b +  9216 + 16,    asrc_l + k0 + 8);
        cp16(b + 18432,         bsrc_h + k0);
        cp16(b + 18432 + 16,    bsrc_h + k0 + 8);
        cp16(b + 27648,         bsrc_l + k0);
        cp16(b + 27648 + 16,    bsrc_l + k0 + 8);
    };

    issue(0, 0);
    CP_COMMIT();

    for (int kk = 0; kk < 16; kk++) {
        const int s = kk & 1;
        if (kk < 15) {
            issue(s ^ 1, (kk + 1) * 64);
            CP_COMMIT();
            CP_WAIT(1);
        } else {
            CP_WAIT(0);
        }
        __syncthreads();

        const unsigned short* Ahi = reinterpret_cast<const unsigned short*>(sg + s * STG_BYTES);
        const unsigned short* Alo = Ahi + 4608;
        const unsigned short* Bhi = Ahi + 9216;
        const unsigned short* Blo = Ahi + 13824;

        #pragma unroll
        for (int ks = 0; ks < 4; ks++) {
            const int ka = ks * 16 + 2 * t4;
            const int ar0 = mt * 16 + g, ar1 = ar0 + 8;
            unsigned ah0 = *(const unsigned*)T72(Ahi, ar0, ka);
            unsigned ah1 = *(const unsigned*)T72(Ahi, ar1, ka);
            unsigned ah2 = *(const unsigned*)T72(Ahi, ar0, ka + 8);
            unsigned ah3 = *(const unsigned*)T72(Ahi, ar1, ka + 8);
            unsigned al0 = *(const unsigned*)T72(Alo, ar0, ka);
            unsigned al1 = *(const unsigned*)T72(Alo, ar1, ka);
            unsigned al2 = *(const unsigned*)T72(Alo, ar0, ka + 8);
            unsigned al3 = *(const unsigned*)T72(Alo, ar1, ka + 8);
            #pragma unroll
            for (int nt = 0; nt < 4; nt++) {
                const int n = nh * 32 + nt * 8 + g;
                unsigned bh0 = *(const unsigned*)T72(Bhi, n, ka);
                unsigned bh1 = *(const unsigned*)T72(Bhi, n, ka + 8);
                unsigned bl0 = *(const unsigned*)T72(Blo, n, ka);
                unsigned bl1 = *(const unsigned*)T72(Blo, n, ka + 8);
                mma_bf16(acc[nt], ah0, ah1, ah2, ah3, bh0, bh1);
                mma_bf16(acc[nt], ah0, ah1, ah2, ah3, bl0, bl1);
                mma_bf16(acc[nt], al0, al1, al2, al3, bh0, bh1);
            }
        }
        __syncthreads();
    }

    #pragma unroll
    for (int nt = 0; nt < 4; nt++) {
        const int col = n0 + nh * 32 + nt * 8 + 2 * t4;
        const int r0 = m0 + mt * 16 + g;
        float2 bb = *reinterpret_cast<const float2*>(&bias[col]);
        float2 v0 = { acc[nt][0] + bb.x, acc[nt][1] + bb.y };
        float2 v1 = { acc[nt][2] + bb.x, acc[nt][3] + bb.y };
        *reinterpret_cast<float2*>(&g_xp[(size_t)r0 * DIM + col]) = v0;
        *reinterpret_cast<float2*>(&g_xp[(size_t)(r0 + 8) * DIM + col]) = v1;
    }
}

// ---------------------------------------------------------------------------
// Kernel 2: persistent recurrence — B in registers, K-split across 8 warps.
// Warp w: K range [w*128, (w+1)*128), full 32x32 output; 8-way smem reduction.
// Dynamic smem: A stage [2 halves][32 rows][1032] bf16 (132096 B)
//             + partials [8][32][36] fp32 (36864 B)
// ---------------------------------------------------------------------------
__global__ __launch_bounds__(THREADS_R, 1) void rnn_rec_kernel(
    const float* __restrict__ h0,
    const float* __restrict__ Wh,
    float* __restrict__ out)
{
    extern __shared__ char s_dyn[];
    __nv_bfloat16* s_a = reinterpret_cast<__nv_bfloat16*>(s_dyn);
    float* s_p = reinterpret_cast<float*>(s_dyn + A_BYTES);
    const uint32_t s_a_u32 = smem_u32(s_a);

    const int tid = threadIdx.x, lane = tid & 31, wid = tid >> 5;
    const int g = lane >> 2, t4 = lane & 3;
    const int mblk = blockIdx.x >> 5;
    const int nstrip = blockIdx.x & 31;
    const int m0 = mblk * 32, n0 = nstrip * 32;

    // ---- B (Wh) fragments: registers, loaded once ----
    uint4 breg[8][4];
    #pragma unroll
    for (int ks = 0; ks < 8; ks++) {
        #pragma unroll
        for (int nt = 0; nt < 4; nt++) {
            const int kb = (wid * 8 + ks) * 16 + 2 * t4;
            const int n = n0 + nt * 8 + g;
            float w00 = __ldg(&Wh[(size_t)(kb + 0) * DIM + n]);
            float w01 = __ldg(&Wh[(size_t)(kb + 1) * DIM + n]);
            float w10 = __ldg(&Wh[(size_t)(kb + 8) * DIM + n]);
            float w11 = __ldg(&Wh[(size_t)(kb + 9) * DIM + n]);
            unsigned short h00, l00, h01, l01, h10, l10, h11, l11;
            split2(w00, h00, l00); split2(w01, h01, l01);
            split2(w10, h10, l10); split2(w11, h11, l11);
            breg[ks][nt] = make_uint4(pck(h00, h01), pck(h10, h11),
                                      pck(l00, l01), pck(l10, l11));
        }
    }

    // ---- init: write own strip of H0, publish flag = 1 ----
    for (int i = tid; i < 32 * 32; i += THREADS_R) {
        const int r = i >> 5, cc = i & 31;
        unsigned short hi, lo;
        split2(h0[(size_t)(m0 + r) * DIM + n0 + cc], hi, lo);
        g_hh[0][(size_t)(m0 + r) * DIM + n0 + cc] = __ushort_as_bfloat16(hi);
        g_hl[0][(size_t)(m0 + r) * DIM + n0 + cc] = __ushort_as_bfloat16(lo);
    }
    __syncthreads();
    if (tid == 0) st_rel(&g_flag[mblk][nstrip * 32], 1u);

    // epilogue mapping: thread -> (row er, cols ec..ec+3)
    const int er = tid >> 3;
    const int ec = (tid & 7) * 4;

    // ldmatrix lane address component (within a half)
    const uint32_t a_lane = (uint32_t)((lane & 15) * AROW + wid * 128 + (lane >> 4) * 8) * 2;

    for (int t = 0; t < SEQ; t++) {
        const int rb = t & 1, wb = rb ^ 1;
        const __nv_bfloat16* Hh = g_hh[rb];
        const __nv_bfloat16* Hl = g_hl[rb];
        const unsigned tgt = (unsigned)(t + 1);

        // xp prefetch (independent of H)
        const size_t obase = ((size_t)t * BATCH + m0 + er) * DIM + n0 + ec;
        const float4 xv = __ldg(reinterpret_cast<const float4*>(&g_xp[obase]));

        // warp 0 polls all 32 producer strips (lane i -> strip i)
        if (wid == 0) {
            const unsigned* fp = &g_flag[mblk][lane * 32];
            while (ld_acq(fp) < tgt) { }
        }
        __syncthreads();

        // stage full A (hi+lo), two commit groups by m-half
        #pragma unroll
        for (int grp = 0; grp < 2; grp++) {
            #pragma unroll
            for (int i = 0; i < 16; i++) {
                const int idx = tid + i * 256;          // 0..4095
                const int half = idx >> 11;
                const int row = grp * 16 + ((idx >> 7) & 15);
                const int seg = idx & 127;
                const __nv_bfloat16* src =
                    (half ? Hl : Hh) + (size_t)(m0 + row) * DIM + seg * 8;
                const uint32_t dst = s_a_u32 +
                    (uint32_t)(half * AHALF + row * AROW + seg * 8) * 2;
                cp16(dst, src);
            }
            CP_COMMIT();
        }

        float c[2][4][4];
        #pragma unroll
        for (int mt = 0; mt < 2; mt++)
            #pragma unroll
            for (int nt = 0; nt < 4; nt++)
                #pragma unroll
                for (int v = 0; v < 4; v++) c[mt][nt][v] = 0.f;

        #pragma unroll
        for (int mt = 0; mt < 2; mt++) {
            if (mt == 0) { CP_WAIT(1); } else { CP_WAIT(0); }
            __syncthreads();
            const uint32_t ab = s_a_u32 + (uint32_t)(mt * 16 * AROW) * 2 + a_lane;
            #pragma unroll
            for (int ks = 0; ks < 8; ks++) {
                unsigned ah0, ah1, ah2, ah3, al0, al1, al2, al3;
                ldsm4(ah0, ah1, ah2, ah3, ab + ks * 32);
                ldsm4(al0, al1, al2, al3, ab + (uint32_t)AHALF * 2 + ks * 32);
                #pragma unroll
                for (int nt = 0; nt < 4; nt++) {
                    const uint4 bb = breg[ks][nt];
                    mma_bf16(c[mt][nt], ah0, ah1, ah2, ah3, bb.x, bb.y);
                    mma_bf16(c[mt][nt], ah0, ah1, ah2, ah3, bb.z, bb.w);
                    mma_bf16(c[mt][nt], al0, al1, al2, al3, bb.x, bb.y);
                }
            }
        }

        // ---- write partials [w][row][36] ----
        #pragma unroll
        for (int mt = 0; mt < 2; mt++) {
            #pragma unroll
            for (int nt = 0; nt < 4; nt++) {
                const int row = mt * 16 + g;
                const int cc = nt * 8 + 2 * t4;
                float* p0 = &s_p[(wid * 32 + row) * 36 + cc];
                p0[0] = c[mt][nt][0]; p0[1] = c[mt][nt][1];
                float* p1 = &s_p[(wid * 32 + row + 8) * 36 + cc];
                p1[0] = c[mt][nt][2]; p1[1] = c[mt][nt][3];
            }
        }
        __syncthreads();

        // ---- reduce 8 warps + epilogue ----
        float4 s = {0.f, 0.f, 0.f, 0.f};
        #pragma unroll
        for (int w = 0; w < 8; w++) {
            const float4 p = *reinterpret_cast<const float4*>(&s_p[(w * 32 + er) * 36 + ec]);
            s.x += p.x; s.y += p.y; s.z += p.z; s.w += p.w;
        }
        const float v0 = tanhf(s.x + xv.x);
        const float v1 = tanhf(s.y + xv.y);
        const float v2 = tanhf(s.z + xv.z);
        const float v3 = tanhf(s.w + xv.w);

        // publish next H first
        {
            unsigned short h0s, l0s, h1s, l1s, h2s, l2s, h3s, l3s;
            split2(v0, h0s, l0s); split2(v1, h1s, l1s);
            split2(v2, h2s, l2s); split2(v3, h3s, l3s);
            const size_t hoff = (size_t)(m0 + er) * DIM + n0 + ec;
            uint2 hh = { pck(h0s, h1s), pck(h2s, h3s) };
            uint2 hl = { pck(l0s, l1s), pck(l2s, l3s) };
            *reinterpret_cast<uint2*>(&g_hh[wb][hoff]) = hh;
            *reinterpret_cast<uint2*>(&g_hl[wb][hoff]) = hl;
        }
        __syncthreads();
        if (tid == 0) st_rel(&g_flag[mblk][nstrip * 32], (unsigned)(t + 2));

        const float4 ov = { v0, v1, v2, v3 };
        *reinterpret_cast<float4*>(&out[obase]) = ov;
    }
}

// ---------------------------------------------------------------------------
// Launcher: inputs: x, h0, Wx, Wh, b
// ---------------------------------------------------------------------------
extern "C" void kernel_launch(void* const* d_in, const int* in_sizes, int n_in,
                              void* d_out, int out_size)
{
    const float* x  = (const float*)d_in[0];
    const float* h0 = (const float*)d_in[1];
    const float* Wx = (const float*)d_in[2];
    const float* Wh = (const float*)d_in[3];
    const float* b  = (const float*)d_in[4];
    float* out = (float*)d_out;

    cudaFuncSetAttribute(rnn_rec_kernel,
                         cudaFuncAttributeMaxDynamicSharedMemorySize, DYN_R);
    cudaFuncSetAttribute(gemm_xp_mma,
                         cudaFuncAttributeMaxDynamicSharedMemorySize, 2 * STG_BYTES);

    void* f0 = nullptr;
    cudaGetSymbolAddress(&f0, g_flag);
    cudaMemsetAsync(f0, 0, sizeof(unsigned) * 4 * 32 * 32);

    split_x_kernel<<<2048, 256>>>(x);
    {
        dim3 grid(DIM / 32, DIM / 32);
        split_wt_kernel<<<grid, 256>>>(Wx);
    }
    {
        dim3 grid(DIM / 64, (SEQ * BATCH) / 64);
        gemm_xp_mma<<<grid, 256, 2 * STG_BYTES>>>(b);
    }
    rnn_rec_kernel<<<GRID_R, THREADS_R, DYN_R>>>(h0, Wh, out);
}

// round 13
// speedup vs baseline: 4.7615x; 1.0533x over previous
#include <cuda_runtime.h>
#include <cuda_bf16.h>
#include <math.h>
#include <stdint.h>

#define SEQ 128
#define BATCH 128
#define DIM 1024
#define KD2 (DIM / 2)

#define GRID_R 128
#define THREADS_R 256

#define WROW 136                    // per-warp A row stride (elements), 272 B
#define WHALF (32 * WROW)           // 4352 elements (8704 B)
#define WSLICE (2 * WHALF)          // hi+lo, 17408 B
#define A_BYTES (8 * WSLICE * 2)    // 139264? (elements*2) -> careful: WSLICE in elems
#define P_OFF (8 * WSLICE * 2)      // bytes offset of partials = 8*17408 = 139264
#define P_BYTES (8 * 32 * 36 * 4)   // 36864
#define DYN_R (P_OFF + P_BYTES)     // 176128

// ---------------------------------------------------------------------------
// Global scratch
// ---------------------------------------------------------------------------
__device__ float g_xp[(size_t)SEQ * BATCH * DIM];
__device__ __nv_bfloat16 g_hh[2][BATCH * DIM];
__device__ __nv_bfloat16 g_hl[2][BATCH * DIM];
__device__ __align__(16) unsigned short g_xhi[(size_t)SEQ * BATCH * DIM];
__device__ __align__(16) unsigned short g_xlo[(size_t)SEQ * BATCH * DIM];
__device__ __align__(16) unsigned short g_wthi[DIM * DIM];
__device__ __align__(16) unsigned short g_wtlo[DIM * DIM];
__device__ unsigned g_flag[4][32 * 32];   // [group][strip*32] 128B-strided

// ---------------------------------------------------------------------------
// Helpers
// ---------------------------------------------------------------------------
__device__ __forceinline__ void split2(float v, unsigned short& hi, unsigned short& lo) {
    __nv_bfloat16 h = __float2bfloat16(v);
    __nv_bfloat16 l = __float2bfloat16(v - __bfloat162float(h));
    hi = __bfloat16_as_ushort(h);
    lo = __bfloat16_as_ushort(l);
}
__device__ __forceinline__ unsigned pck(unsigned short a, unsigned short b) {
    return ((unsigned)b << 16) | (unsigned)a;
}
__device__ __forceinline__ uint32_t smem_u32(const void* p) {
    uint32_t a;
    asm("{ .reg .u64 t; cvta.to.shared.u64 t, %1; cvt.u32.u64 %0, t; }"
        : "=r"(a) : "l"(p));
    return a;
}
__device__ __forceinline__ void mma_bf16(float c[4],
                                         unsigned a0, unsigned a1, unsigned a2, unsigned a3,
                                         unsigned b0, unsigned b1) {
    asm volatile(
        "mma.sync.aligned.m16n8k16.row.col.f32.bf16.bf16.f32 "
        "{%0,%1,%2,%3}, {%4,%5,%6,%7}, {%8,%9}, {%0,%1,%2,%3};"
        : "+f"(c[0]), "+f"(c[1]), "+f"(c[2]), "+f"(c[3])
        : "r"(a0), "r"(a1), "r"(a2), "r"(a3), "r"(b0), "r"(b1));
}
__device__ __forceinline__ void ldsm4(unsigned& r0, unsigned& r1, unsigned& r2, unsigned& r3,
                                      uint32_t addr) {
    asm volatile("ldmatrix.sync.aligned.m8n8.x4.shared.b16 {%0,%1,%2,%3}, [%4];"
                 : "=r"(r0), "=r"(r1), "=r"(r2), "=r"(r3) : "r"(addr));
}
__device__ __forceinline__ void cp16(uint32_t dst, const void* src) {
    asm volatile("cp.async.cg.shared.global [%0], [%1], 16;" :: "r"(dst), "l"(src));
}
#define CP_COMMIT() asm volatile("cp.async.commit_group;" ::: "memory")
#define CP_WAIT(n)  asm volatile("cp.async.wait_group %0;" :: "n"(n) : "memory")

__device__ __forceinline__ void st_rel(unsigned* p, unsigned v) {
    asm volatile("st.release.gpu.global.u32 [%0], %1;" :: "l"(p), "r"(v) : "memory");
}
__device__ __forceinline__ unsigned ld_acq(const unsigned* p) {
    unsigned v;
    asm volatile("ld.acquire.gpu.global.u32 %0, [%1];" : "=r"(v) : "l"(p) : "memory");
    return v;
}

// ---------------------------------------------------------------------------
// Split kernels (unchanged)
// ---------------------------------------------------------------------------
__global__ __launch_bounds__(256) void split_x_kernel(const float* __restrict__ src) {
    const size_t N = (size_t)SEQ * BATCH * DIM;
    for (size_t i = ((size_t)blockIdx.x * 256 + threadIdx.x) * 8; i < N;
         i += (size_t)gridDim.x * 256 * 8) {
        float4 v0 = *reinterpret_cast<const float4*>(src + i);
        float4 v1 = *reinterpret_cast<const float4*>(src + i + 4);
        unsigned short h[8], l[8];
        split2(v0.x, h[0], l[0]); split2(v0.y, h[1], l[1]);
        split2(v0.z, h[2], l[2]); split2(v0.w, h[3], l[3]);
        split2(v1.x, h[4], l[4]); split2(v1.y, h[5], l[5]);
        split2(v1.z, h[6], l[6]); split2(v1.w, h[7], l[7]);
        uint4 ph = { pck(h[0],h[1]), pck(h[2],h[3]), pck(h[4],h[5]), pck(h[6],h[7]) };
        uint4 pl = { pck(l[0],l[1]), pck(l[2],l[3]), pck(l[4],l[5]), pck(l[6],l[7]) };
        *reinterpret_cast<uint4*>(&g_xhi[i]) = ph;
        *reinterpret_cast<uint4*>(&g_xlo[i]) = pl;
    }
}

__global__ __launch_bounds__(256) void split_wt_kernel(const float* __restrict__ W) {
    __shared__ unsigned short shi[32][33], slo[32][33];
    const int k0 = blockIdx.x * 32, n0 = blockIdx.y * 32;
    const int tid = threadIdx.x;
    #pragma unroll
    for (int j = 0; j < 4; j++) {
        const int idx = tid + j * 256;
        const int kk = idx >> 5, nn = idx & 31;
        float v = W[(size_t)(k0 + kk) * DIM + n0 + nn];
        unsigned short h, l;
        split2(v, h, l);
        shi[nn][kk] = h; slo[nn][kk] = l;
    }
    __syncthreads();
    #pragma unroll
    for (int j = 0; j < 4; j++) {
        const int idx = tid + j * 256;
        const int nn = idx >> 5, kk = idx & 31;
        g_wthi[(size_t)(n0 + nn) * DIM + k0 + kk] = shi[nn][kk];
        g_wtlo[(size_t)(n0 + nn) * DIM + k0 + kk] = slo[nn][kk];
    }
}

// ---------------------------------------------------------------------------
// Kernel 1: xp = X @ Wx + b, pure-bf16 double-buffered (unchanged)
// ---------------------------------------------------------------------------
#define STG_BYTES 36864
#define T72(p, r, c) ((p) + (r) * 72 + (c))

__global__ __launch_bounds__(256) void gemm_xp_mma(const float* __restrict__ bias)
{
    extern __shared__ char sg[];
    const uint32_t sbase = smem_u32(sg);

    const int tid = threadIdx.x, lane = tid & 31, wid = tid >> 5;
    const int m0 = blockIdx.y * 64, n0 = blockIdx.x * 64;
    const int g = lane >> 2, t4 = lane & 3;
    const int mt = wid >> 1;
    const int nh = wid & 1;

    const int lrow = tid >> 2;
    const int lcb  = (tid & 3) * 16;

    const unsigned short* asrc_h = &g_xhi[(size_t)(m0 + lrow) * DIM + lcb];
    const unsigned short* asrc_l = &g_xlo[(size_t)(m0 + lrow) * DIM + lcb];
    const unsigned short* bsrc_h = &g_wthi[(size_t)(n0 + lrow) * DIM + lcb];
    const unsigned short* bsrc_l = &g_wtlo[(size_t)(n0 + lrow) * DIM + lcb];
    const uint32_t drow = (uint32_t)(lrow * 72 + lcb) * 2;

    float acc[4][4] = {};

    auto issue = [&](int s, int k0) {
        const uint32_t b = sbase + s * STG_BYTES + drow;
        cp16(b,                 asrc_h + k0);
        cp16(b + 16,            asrc_h + k0 + 8);
        cp16(b +  9216,         asrc_l + k0);
        cp16(b +  9216 + 16,    asrc_l + k0 + 8);
        cp16(b + 18432,         bsrc_h + k0);
        cp16(b + 18432 + 16,    bsrc_h + k0 + 8);
        cp16(b + 27648,         bsrc_l + k0);
        cp16(b + 27648 + 16,    bsrc_l + k0 + 8);
    };

    issue(0, 0);
    CP_COMMIT();

    for (int kk = 0; kk < 16; kk++) {
        const int s = kk & 1;
        if (kk < 15) {
            issue(s ^ 1, (kk + 1) * 64);
            CP_COMMIT();
            CP_WAIT(1);
        } else {
            CP_WAIT(0);
        }
        __syncthreads();

        const unsigned short* Ahi = reinterpret_cast<const unsigned short*>(sg + s * STG_BYTES);
        const unsigned short* Alo = Ahi + 4608;
        const unsigned short* Bhi = Ahi + 9216;
        const unsigned short* Blo = Ahi + 13824;

        #pragma unroll
        for (int ks = 0; ks < 4; ks++) {
            const int ka = ks * 16 + 2 * t4;
            const int ar0 = mt * 16 + g, ar1 = ar0 + 8;
            unsigned ah0 = *(const unsigned*)T72(Ahi, ar0, ka);
            unsigned ah1 = *(const unsigned*)T72(Ahi, ar1, ka);
            unsigned ah2 = *(const unsigned*)T72(Ahi, ar0, ka + 8);
            unsigned ah3 = *(const unsigned*)T72(Ahi, ar1, ka + 8);
            unsigned al0 = *(const unsigned*)T72(Alo, ar0, ka);
            unsigned al1 = *(const unsigned*)T72(Alo, ar1, ka);
            unsigned al2 = *(const unsigned*)T72(Alo, ar0, ka + 8);
            unsigned al3 = *(const unsigned*)T72(Alo, ar1, ka + 8);
            #pragma unroll
            for (int nt = 0; nt < 4; nt++) {
                const int n = nh * 32 + nt * 8 + g;
                unsigned bh0 = *(const unsigned*)T72(Bhi, n, ka);
                unsigned bh1 = *(const unsigned*)T72(Bhi, n, ka + 8);
                unsigned bl0 = *(const unsigned*)T72(Blo, n, ka);
                unsigned bl1 = *(const unsigned*)T72(Blo, n, ka + 8);
                mma_bf16(acc[nt], ah0, ah1, ah2, ah3, bh0, bh1);
                mma_bf16(acc[nt], ah0, ah1, ah2, ah3, bl0, bl1);
                mma_bf16(acc[nt], al0, al1, al2, al3, bh0, bh1);
            }
        }
        __syncthreads();
    }

    #pragma unroll
    for (int nt = 0; nt < 4; nt++) {
        const int col = n0 + nh * 32 + nt * 8 + 2 * t4;
        const int r0 = m0 + mt * 16 + g;
        float2 bb = *reinterpret_cast<const float2*>(&bias[col]);
        float2 v0 = { acc[nt][0] + bb.x, acc[nt][1] + bb.y };
        float2 v1 = { acc[nt][2] + bb.x, acc[nt][3] + bb.y };
        *reinterpret_cast<float2*>(&g_xp[(size_t)r0 * DIM + col]) = v0;
        *reinterpret_cast<float2*>(&g_xp[(size_t)(r0 + 8) * DIM + col]) = v1;
    }
}

// ---------------------------------------------------------------------------
// Kernel 2: persistent recurrence — per-warp dataflow.
// Warp w: K range [128w, 128w+128) -> depends ONLY on producer strips 4w..4w+3.
// Each warp: poll own 4 flags -> cp.async own 16KB slice -> MMA -> partials.
// One CTA sync, 8-way reduction, epilogue.
// Dynamic smem: 8 warp slices [2 half][32 rows][136] bf16 (139264 B)
//             + partials [8][32][36] fp32 (36864 B)
// ---------------------------------------------------------------------------
__global__ __launch_bounds__(THREADS_R, 1) void rnn_rec_kernel(
    const float* __restrict__ h0,
    const float* __restrict__ Wh,
    float* __restrict__ out)
{
    extern __shared__ char s_dyn[];
    float* s_p = reinterpret_cast<float*>(s_dyn + P_OFF);
    const uint32_t s_a_u32 = smem_u32(s_dyn);

    const int tid = threadIdx.x, lane = tid & 31, wid = tid >> 5;
    const int g = lane >> 2, t4 = lane & 3;
    const int mblk = blockIdx.x >> 5;
    const int nstrip = blockIdx.x & 31;
    const int m0 = mblk * 32, n0 = nstrip * 32;

    // ---- B (Wh) fragments: registers, loaded once; warp w owns K [128w,128w+128)
    uint4 breg[8][4];
    #pragma unroll
    for (int ks = 0; ks < 8; ks++) {
        #pragma unroll
        for (int nt = 0; nt < 4; nt++) {
            const int kb = (wid * 8 + ks) * 16 + 2 * t4;
            const int n = n0 + nt * 8 + g;
            float w00 = __ldg(&Wh[(size_t)(kb + 0) * DIM + n]);
            float w01 = __ldg(&Wh[(size_t)(kb + 1) * DIM + n]);
            float w10 = __ldg(&Wh[(size_t)(kb + 8) * DIM + n]);
            float w11 = __ldg(&Wh[(size_t)(kb + 9) * DIM + n]);
            unsigned short h00, l00, h01, l01, h10, l10, h11, l11;
            split2(w00, h00, l00); split2(w01, h01, l01);
            split2(w10, h10, l10); split2(w11, h11, l11);
            breg[ks][nt] = make_uint4(pck(h00, h01), pck(h10, h11),
                                      pck(l00, l01), pck(l10, l11));
        }
    }

    // ---- init: write own strip of H0, publish flag = 1 ----
    for (int i = tid; i < 32 * 32; i += THREADS_R) {
        const int r = i >> 5, cc = i & 31;
        unsigned short hi, lo;
        split2(h0[(size_t)(m0 + r) * DIM + n0 + cc], hi, lo);
        g_hh[0][(size_t)(m0 + r) * DIM + n0 + cc] = __ushort_as_bfloat16(hi);
        g_hl[0][(size_t)(m0 + r) * DIM + n0 + cc] = __ushort_as_bfloat16(lo);
    }
    __syncthreads();
    if (tid == 0) st_rel(&g_flag[mblk][nstrip * 32], 1u);

    // epilogue mapping
    const int er = tid >> 3;
    const int ec = (tid & 7) * 4;

    // per-warp smem slice
    const uint32_t wbase = s_a_u32 + (uint32_t)wid * (WSLICE * 2);
    // cp.async per-lane constants: seg = lane&15 (8-elem segment), rowpar = lane>>4
    const int seg = lane & 15;
    const int rowpar = lane >> 4;
    const int kw0 = wid * 128;                    // this warp's K origin
    // ldmatrix lane address (within slice half): row = lane&15 (+mt*16), col off
    const uint32_t a_lane = (uint32_t)((lane & 15) * WROW + (lane >> 4) * 8) * 2;
    // own 4 producer flags (lanes 0..3 poll)
    const unsigned* fpw = &g_flag[mblk][((wid << 2) + (lane & 3)) * 32];

    for (int t = 0; t < SEQ; t++) {
        const int rb = t & 1, wb = rb ^ 1;
        const __nv_bfloat16* Hh = g_hh[rb];
        const __nv_bfloat16* Hl = g_hl[rb];
        const unsigned tgt = (unsigned)(t + 1);

        // xp prefetch (independent of H)
        const size_t obase = ((size_t)t * BATCH + m0 + er) * DIM + n0 + ec;
        const float4 xv = __ldg(reinterpret_cast<const float4*>(&g_xp[obase]));

        // ---- per-warp: wait own 4 strips ----
        if (lane < 4) {
            while (ld_acq(fpw) < tgt) { }
        }
        __syncwarp();

        // ---- per-warp: stage own 16KB slice (hi+lo) ----
        #pragma unroll
        for (int i = 0; i < 16; i++) {
            const int row = ((i << 1) | rowpar);                 // 0..31
            const __nv_bfloat16* srch = Hh + (size_t)(m0 + row) * DIM + kw0 + seg * 8;
            const __nv_bfloat16* srcl = Hl + (size_t)(m0 + row) * DIM + kw0 + seg * 8;
            const uint32_t d = wbase + (uint32_t)(row * WROW + seg * 8) * 2;
            cp16(d, srch);
            cp16(d + WHALF * 2, srcl);
        }
        CP_COMMIT();
        CP_WAIT(0);
        __syncwarp();

        // ---- MMA ----
        float c[2][4][4];
        #pragma unroll
        for (int mt = 0; mt < 2; mt++)
            #pragma unroll
            for (int nt = 0; nt < 4; nt++)
                #pragma unroll
                for (int v = 0; v < 4; v++) c[mt][nt][v] = 0.f;

        #pragma unroll
        for (int mt = 0; mt < 2; mt++) {
            const uint32_t ab = wbase + (uint32_t)(mt * 16 * WROW) * 2 + a_lane;
            #pragma unroll
            for (int ks = 0; ks < 8; ks++) {
                unsigned ah0, ah1, ah2, ah3, al0, al1, al2, al3;
                ldsm4(ah0, ah1, ah2, ah3, ab + ks * 32);
                ldsm4(al0, al1, al2, al3, ab + (uint32_t)WHALF * 2 + ks * 32);
                #pragma unroll
                for (int nt = 0; nt < 4; nt++) {
                    const uint4 bb = breg[ks][nt];
                    mma_bf16(c[mt][nt], ah0, ah1, ah2, ah3, bb.x, bb.y);
                    mma_bf16(c[mt][nt], ah0, ah1, ah2, ah3, bb.z, bb.w);
                    mma_bf16(c[mt][nt], al0, al1, al2, al3, bb.x, bb.y);
                }
            }
        }

        // ---- partials [w][row][36] ----
        #pragma unroll
        for (int mt = 0; mt < 2; mt++) {
            #pragma unroll
            for (int nt = 0; nt < 4; nt++) {
                const int row = mt * 16 + g;
                const int cc = nt * 8 + 2 * t4;
                float* p0 = &s_p[(wid * 32 + row) * 36 + cc];
                p0[0] = c[mt][nt][0]; p0[1] = c[mt][nt][1];
                float* p1 = &s_p[(wid * 32 + row + 8) * 36 + cc];
                p1[0] = c[mt][nt][2]; p1[1] = c[mt][nt][3];
            }
        }
        __syncthreads();

        // ---- reduce 8 warps + epilogue ----
        float4 s = {0.f, 0.f, 0.f, 0.f};
        #pragma unroll
        for (int w = 0; w < 8; w++) {
            const float4 p = *reinterpret_cast<const float4*>(&s_p[(w * 32 + er) * 36 + ec]);
            s.x += p.x; s.y += p.y; s.z += p.z; s.w += p.w;
        }
        const float v0 = tanhf(s.x + xv.x);
        const float v1 = tanhf(s.y + xv.y);
        const float v2 = tanhf(s.z + xv.z);
        const float v3 = tanhf(s.w + xv.w);

        // publish next H
        {
            unsigned short h0s, l0s, h1s, l1s, h2s, l2s, h3s, l3s;
            split2(v0, h0s, l0s); split2(v1, h1s, l1s);
            split2(v2, h2s, l2s); split2(v3, h3s, l3s);
            const size_t hoff = (size_t)(m0 + er) * DIM + n0 + ec;
            uint2 hh = { pck(h0s, h1s), pck(h2s, h3s) };
            uint2 hl = { pck(l0s, l1s), pck(l2s, l3s) };
            *reinterpret_cast<uint2*>(&g_hh[wb][hoff]) = hh;
            *reinterpret_cast<uint2*>(&g_hl[wb][hoff]) = hl;
        }
        __syncthreads();
        if (tid == 0) st_rel(&g_flag[mblk][nstrip * 32], (unsigned)(t + 2));

        const float4 ov = { v0, v1, v2, v3 };
        *reinterpret_cast<float4*>(&out[obase]) = ov;
    }
}

// ---------------------------------------------------------------------------
// Launcher: inputs: x, h0, Wx, Wh, b
// ---------------------------------------------------------------------------
extern "C" void kernel_launch(void* const* d_in, const int* in_sizes, int n_in,
                              void* d_out, int out_size)
{
    const float* x  = (const float*)d_in[0];
    const float* h0 = (const float*)d_in[1];
    const float* Wx = (const float*)d_in[2];
    const float* Wh = (const float*)d_in[3];
    const float* b  = (const float*)d_in[4];
    float* out = (float*)d_out;

    cudaFuncSetAttribute(rnn_rec_kernel,
                         cudaFuncAttributeMaxDynamicSharedMemorySize, DYN_R);
    cudaFuncSetAttribute(gemm_xp_mma,
                         cudaFuncAttributeMaxDynamicSharedMemorySize, 2 * STG_BYTES);

    void* f0 = nullptr;
    cudaGetSymbolAddress(&f0, g_flag);
    cudaMemsetAsync(f0, 0, sizeof(unsigned) * 4 * 32 * 32);

    split_x_kernel<<<2048, 256>>>(x);
    {
        dim3 grid(DIM / 32, DIM / 32);
        split_wt_kernel<<<grid, 256>>>(Wx);
    }
    {
        dim3 grid(DIM / 64, (SEQ * BATCH) / 64);
        gemm_xp_mma<<<grid, 256, 2 * STG_BYTES>>>(b);
    }
    rnn_rec_kernel<<<GRID_R, THREADS_R, DYN_R>>>(h0, Wh, out);
}

// round 14
// speedup vs baseline: 5.0656x; 1.0639x over previous
#include <cuda_runtime.h>
#include <cuda_bf16.h>
#include <math.h>
#include <stdint.h>

#define SEQ 128
#define BATCH 128
#define DIM 1024
#define KD2 (DIM / 2)

#define GRID_R 128
#define THREADS_R 256

#define WROW 136                    // per-warp A row stride (elements), 272 B
#define WHALF (32 * WROW)           // elements per half
#define WSLICE (2 * WHALF)          // hi+lo elements
#define P_OFF (8 * WSLICE * 2)      // bytes offset of partials = 139264
#define P_BYTES (8 * 32 * 36 * 4)   // 36864
#define DYN_R (P_OFF + P_BYTES)     // 176128

// ---------------------------------------------------------------------------
// Global scratch
// ---------------------------------------------------------------------------
__device__ float g_xp[(size_t)SEQ * BATCH * DIM];
__device__ __nv_bfloat16 g_hh[2][BATCH * DIM];
__device__ __nv_bfloat16 g_hl[2][BATCH * DIM];
__device__ __align__(16) unsigned short g_xhi[(size_t)SEQ * BATCH * DIM];
__device__ __align__(16) unsigned short g_xlo[(size_t)SEQ * BATCH * DIM];
__device__ __align__(16) unsigned short g_wthi[DIM * DIM];
__device__ __align__(16) unsigned short g_wtlo[DIM * DIM];
__device__ unsigned g_flag[4][32 * 32];

// ---------------------------------------------------------------------------
// Helpers
// ---------------------------------------------------------------------------
__device__ __forceinline__ void split2(float v, unsigned short& hi, unsigned short& lo) {
    __nv_bfloat16 h = __float2bfloat16(v);
    __nv_bfloat16 l = __float2bfloat16(v - __bfloat162float(h));
    hi = __bfloat16_as_ushort(h);
    lo = __bfloat16_as_ushort(l);
}
__device__ __forceinline__ unsigned pck(unsigned short a, unsigned short b) {
    return ((unsigned)b << 16) | (unsigned)a;
}
__device__ __forceinline__ uint32_t smem_u32(const void* p) {
    uint32_t a;
    asm("{ .reg .u64 t; cvta.to.shared.u64 t, %1; cvt.u32.u64 %0, t; }"
        : "=r"(a) : "l"(p));
    return a;
}
__device__ __forceinline__ void mma_bf16(float c[4],
                                         unsigned a0, unsigned a1, unsigned a2, unsigned a3,
                                         unsigned b0, unsigned b1) {
    asm volatile(
        "mma.sync.aligned.m16n8k16.row.col.f32.bf16.bf16.f32 "
        "{%0,%1,%2,%3}, {%4,%5,%6,%7}, {%8,%9}, {%0,%1,%2,%3};"
        : "+f"(c[0]), "+f"(c[1]), "+f"(c[2]), "+f"(c[3])
        : "r"(a0), "r"(a1), "r"(a2), "r"(a3), "r"(b0), "r"(b1));
}
__device__ __forceinline__ void ldsm4(unsigned& r0, unsigned& r1, unsigned& r2, unsigned& r3,
                                      uint32_t addr) {
    asm volatile("ldmatrix.sync.aligned.m8n8.x4.shared.b16 {%0,%1,%2,%3}, [%4];"
                 : "=r"(r0), "=r"(r1), "=r"(r2), "=r"(r3) : "r"(addr));
}
__device__ __forceinline__ void cp16(uint32_t dst, const void* src) {
    asm volatile("cp.async.cg.shared.global [%0], [%1], 16;" :: "r"(dst), "l"(src));
}
#define CP_COMMIT() asm volatile("cp.async.commit_group;" ::: "memory")
#define CP_WAIT(n)  asm volatile("cp.async.wait_group %0;" :: "n"(n) : "memory")

__device__ __forceinline__ void st_rel(unsigned* p, unsigned v) {
    asm volatile("st.release.gpu.global.u32 [%0], %1;" :: "l"(p), "r"(v) : "memory");
}
__device__ __forceinline__ unsigned ld_acq(const unsigned* p) {
    unsigned v;
    asm volatile("ld.acquire.gpu.global.u32 %0, [%1];" : "=r"(v) : "l"(p) : "memory");
    return v;
}

// ---------------------------------------------------------------------------
// Split kernels (unchanged)
// ---------------------------------------------------------------------------
__global__ __launch_bounds__(256) void split_x_kernel(const float* __restrict__ src) {
    const size_t N = (size_t)SEQ * BATCH * DIM;
    for (size_t i = ((size_t)blockIdx.x * 256 + threadIdx.x) * 8; i < N;
         i += (size_t)gridDim.x * 256 * 8) {
        float4 v0 = *reinterpret_cast<const float4*>(src + i);
        float4 v1 = *reinterpret_cast<const float4*>(src + i + 4);
        unsigned short h[8], l[8];
        split2(v0.x, h[0], l[0]); split2(v0.y, h[1], l[1]);
        split2(v0.z, h[2], l[2]); split2(v0.w, h[3], l[3]);
        split2(v1.x, h[4], l[4]); split2(v1.y, h[5], l[5]);
        split2(v1.z, h[6], l[6]); split2(v1.w, h[7], l[7]);
        uint4 ph = { pck(h[0],h[1]), pck(h[2],h[3]), pck(h[4],h[5]), pck(h[6],h[7]) };
        uint4 pl = { pck(l[0],l[1]), pck(l[2],l[3]), pck(l[4],l[5]), pck(l[6],l[7]) };
        *reinterpret_cast<uint4*>(&g_xhi[i]) = ph;
        *reinterpret_cast<uint4*>(&g_xlo[i]) = pl;
    }
}

__global__ __launch_bounds__(256) void split_wt_kernel(const float* __restrict__ W) {
    __shared__ unsigned short shi[32][33], slo[32][33];
    const int k0 = blockIdx.x * 32, n0 = blockIdx.y * 32;
    const int tid = threadIdx.x;
    #pragma unroll
    for (int j = 0; j < 4; j++) {
        const int idx = tid + j * 256;
        const int kk = idx >> 5, nn = idx & 31;
        float v = W[(size_t)(k0 + kk) * DIM + n0 + nn];
        unsigned short h, l;
        split2(v, h, l);
        shi[nn][kk] = h; slo[nn][kk] = l;
    }
    __syncthreads();
    #pragma unroll
    for (int j = 0; j < 4; j++) {
        const int idx = tid + j * 256;
        const int nn = idx >> 5, kk = idx & 31;
        g_wthi[(size_t)(n0 + nn) * DIM + k0 + kk] = shi[nn][kk];
        g_wtlo[(size_t)(n0 + nn) * DIM + k0 + kk] = slo[nn][kk];
    }
}

// ---------------------------------------------------------------------------
// Kernel 1: xp = X @ Wx + b — fragments now loaded via ldmatrix.x4
// Stage layout (per stage, 36864 B): Ahi[64][72], Alo, Bhi[64][72], Blo
// ---------------------------------------------------------------------------
#define STG_BYTES 36864

__global__ __launch_bounds__(256) void gemm_xp_mma(const float* __restrict__ bias)
{
    extern __shared__ char sg[];
    const uint32_t sbase = smem_u32(sg);

    const int tid = threadIdx.x, lane = tid & 31, wid = tid >> 5;
    const int m0 = blockIdx.y * 64, n0 = blockIdx.x * 64;
    const int g = lane >> 2, t4 = lane & 3;
    const int mt = wid >> 1;      // 0..3 : 16-row tile
    const int nh = wid & 1;       // 0..1 : 32-col half

    const int lrow = tid >> 2;
    const int lcb  = (tid & 3) * 16;

    const unsigned short* asrc_h = &g_xhi[(size_t)(m0 + lrow) * DIM + lcb];
    const unsigned short* asrc_l = &g_xlo[(size_t)(m0 + lrow) * DIM + lcb];
    const unsigned short* bsrc_h = &g_wthi[(size_t)(n0 + lrow) * DIM + lcb];
    const unsigned short* bsrc_l = &g_wtlo[(size_t)(n0 + lrow) * DIM + lcb];
    const uint32_t drow = (uint32_t)(lrow * 72 + lcb) * 2;

    // ldmatrix lane addressing
    // A (m16k16): rows mt*16+(lane&15), half (lane>>4)
    const uint32_t a_loff = (uint32_t)((mt * 16 + (lane & 15)) * 72 + (lane >> 4) * 8) * 2;
    // B (two n8k16 tiles): rows (lane&7)+((lane>>4)<<3), half ((lane>>3)&1)
    const uint32_t b_loff = (uint32_t)((nh * 32 + (lane & 7) + ((lane >> 4) << 3)) * 72
                                       + ((lane >> 3) & 1) * 8) * 2;

    float acc[4][4] = {};

    auto issue = [&](int s, int k0) {
        const uint32_t b = sbase + s * STG_BYTES + drow;
        cp16(b,                 asrc_h + k0);
        cp16(b + 16,            asrc_h + k0 + 8);
        cp16(b +  9216,         asrc_l + k0);
        cp16(b +  9216 + 16,    asrc_l + k0 + 8);
        cp16(b + 18432,         bsrc_h + k0);
        cp16(b + 18432 + 16,    bsrc_h + k0 + 8);
        cp16(b + 27648,         bsrc_l + k0);
        cp16(b + 27648 + 16,    bsrc_l + k0 + 8);
    };

    issue(0, 0);
    CP_COMMIT();

    for (int kk = 0; kk < 16; kk++) {
        const int s = kk & 1;
        if (kk < 15) {
            issue(s ^ 1, (kk + 1) * 64);
            CP_COMMIT();
            CP_WAIT(1);
        } else {
            CP_WAIT(0);
        }
        __syncthreads();

        const uint32_t st = sbase + s * STG_BYTES;
        const uint32_t aH = st + a_loff;
        const uint32_t aL = aH + 9216;
        const uint32_t bH = st + 18432 + b_loff;
        const uint32_t bL = bH + 9216;

        #pragma unroll
        for (int ks = 0; ks < 4; ks++) {
            const uint32_t ko = (uint32_t)ks * 32;
            unsigned ah0, ah1, ah2, ah3, al0, al1, al2, al3;
            ldsm4(ah0, ah1, ah2, ah3, aH + ko);
            ldsm4(al0, al1, al2, al3, aL + ko);
            // B: pair 0 = nt0,nt1 ; pair 1 = nt2,nt3 (16 rows = 2304 B apart)
            unsigned h00, h01, h10, h11, h20, h21, h30, h31;
            unsigned l00, l01, l10, l11, l20, l21, l30, l31;
            ldsm4(h00, h01, h10, h11, bH + ko);
            ldsm4(h20, h21, h30, h31, bH + 2304 + ko);
            ldsm4(l00, l01, l10, l11, bL + ko);
            ldsm4(l20, l21, l30, l31, bL + 2304 + ko);

            mma_bf16(acc[0], ah0, ah1, ah2, ah3, h00, h01);
            mma_bf16(acc[0], ah0, ah1, ah2, ah3, l00, l01);
            mma_bf16(acc[0], al0, al1, al2, al3, h00, h01);

            mma_bf16(acc[1], ah0, ah1, ah2, ah3, h10, h11);
            mma_bf16(acc[1], ah0, ah1, ah2, ah3, l10, l11);
            mma_bf16(acc[1], al0, al1, al2, al3, h10, h11);

            mma_bf16(acc[2], ah0, ah1, ah2, ah3, h20, h21);
            mma_bf16(acc[2], ah0, ah1, ah2, ah3, l20, l21);
            mma_bf16(acc[2], al0, al1, al2, al3, h20, h21);

            mma_bf16(acc[3], ah0, ah1, ah2, ah3, h30, h31);
            mma_bf16(acc[3], ah0, ah1, ah2, ah3, l30, l31);
            mma_bf16(acc[3], al0, al1, al2, al3, h30, h31);
        }
        __syncthreads();
    }

    #pragma unroll
    for (int nt = 0; nt < 4; nt++) {
        const int col = n0 + nh * 32 + nt * 8 + 2 * t4;
        const int r0 = m0 + mt * 16 + g;
        float2 bb = *reinterpret_cast<const float2*>(&bias[col]);
        float2 v0 = { acc[nt][0] + bb.x, acc[nt][1] + bb.y };
        float2 v1 = { acc[nt][2] + bb.x, acc[nt][3] + bb.y };
        *reinterpret_cast<float2*>(&g_xp[(size_t)r0 * DIM + col]) = v0;
        *reinterpret_cast<float2*>(&g_xp[(size_t)(r0 + 8) * DIM + col]) = v1;
    }
}

// ---------------------------------------------------------------------------
// Kernel 2: persistent recurrence — per-warp dataflow, hi/lo split staging
// ---------------------------------------------------------------------------
__global__ __launch_bounds__(THREADS_R, 1) void rnn_rec_kernel(
    const float* __restrict__ h0,
    const float* __restrict__ Wh,
    float* __restrict__ out)
{
    extern __shared__ char s_dyn[];
    float* s_p = reinterpret_cast<float*>(s_dyn + P_OFF);
    const uint32_t s_a_u32 = smem_u32(s_dyn);

    const int tid = threadIdx.x, lane = tid & 31, wid = tid >> 5;
    const int g = lane >> 2, t4 = lane & 3;
    const int mblk = blockIdx.x >> 5;
    const int nstrip = blockIdx.x & 31;
    const int m0 = mblk * 32, n0 = nstrip * 32;

    // ---- B (Wh) fragments: registers, loaded once ----
    uint4 breg[8][4];
    #pragma unroll
    for (int ks = 0; ks < 8; ks++) {
        #pragma unroll
        for (int nt = 0; nt < 4; nt++) {
            const int kb = (wid * 8 + ks) * 16 + 2 * t4;
            const int n = n0 + nt * 8 + g;
            float w00 = __ldg(&Wh[(size_t)(kb + 0) * DIM + n]);
            float w01 = __ldg(&Wh[(size_t)(kb + 1) * DIM + n]);
            float w10 = __ldg(&Wh[(size_t)(kb + 8) * DIM + n]);
            float w11 = __ldg(&Wh[(size_t)(kb + 9) * DIM + n]);
            unsigned short h00, l00, h01, l01, h10, l10, h11, l11;
            split2(w00, h00, l00); split2(w01, h01, l01);
            split2(w10, h10, l10); split2(w11, h11, l11);
            breg[ks][nt] = make_uint4(pck(h00, h01), pck(h10, h11),
                                      pck(l00, l01), pck(l10, l11));
        }
    }

    // ---- init: write own strip of H0, publish flag = 1 ----
    for (int i = tid; i < 32 * 32; i += THREADS_R) {
        const int r = i >> 5, cc = i & 31;
        unsigned short hi, lo;
        split2(h0[(size_t)(m0 + r) * DIM + n0 + cc], hi, lo);
        g_hh[0][(size_t)(m0 + r) * DIM + n0 + cc] = __ushort_as_bfloat16(hi);
        g_hl[0][(size_t)(m0 + r) * DIM + n0 + cc] = __ushort_as_bfloat16(lo);
    }
    __syncthreads();
    if (tid == 0) st_rel(&g_flag[mblk][nstrip * 32], 1u);

    const int er = tid >> 3;
    const int ec = (tid & 7) * 4;

    const uint32_t wbase = s_a_u32 + (uint32_t)wid * (WSLICE * 2);
    const int seg = lane & 15;
    const int rowpar = lane >> 4;
    const int kw0 = wid * 128;
    const uint32_t a_lane = (uint32_t)((lane & 15) * WROW + (lane >> 4) * 8) * 2;
    const unsigned* fpw = &g_flag[mblk][((wid << 2) + (lane & 3)) * 32];

    for (int t = 0; t < SEQ; t++) {
        const int rb = t & 1, wb = rb ^ 1;
        const __nv_bfloat16* Hh = g_hh[rb];
        const __nv_bfloat16* Hl = g_hl[rb];
        const unsigned tgt = (unsigned)(t + 1);

        const size_t obase = ((size_t)t * BATCH + m0 + er) * DIM + n0 + ec;
        const float4 xv = __ldg(reinterpret_cast<const float4*>(&g_xp[obase]));

        // ---- per-warp: wait own 4 strips ----
        if (lane < 4) {
            while (ld_acq(fpw) < tgt) { }
        }
        __syncwarp();

        // ---- stage hi rows (group 1), then lo rows (group 2) ----
        #pragma unroll
        for (int i = 0; i < 16; i++) {
            const int row = ((i << 1) | rowpar);
            cp16(wbase + (uint32_t)(row * WROW + seg * 8) * 2,
                 Hh + (size_t)(m0 + row) * DIM + kw0 + seg * 8);
        }
        CP_COMMIT();
        #pragma unroll
        for (int i = 0; i < 16; i++) {
            const int row = ((i << 1) | rowpar);
            cp16(wbase + (uint32_t)WHALF * 2 + (uint32_t)(row * WROW + seg * 8) * 2,
                 Hl + (size_t)(m0 + row) * DIM + kw0 + seg * 8);
        }
        CP_COMMIT();

        float c[2][4][4];
        #pragma unroll
        for (int mt = 0; mt < 2; mt++)
            #pragma unroll
            for (int nt = 0; nt < 4; nt++)
                #pragma unroll
                for (int v = 0; v < 4; v++) c[mt][nt][v] = 0.f;

        // ---- pass 1: hi x Bh (runs while lo group lands) ----
        CP_WAIT(1);
        __syncwarp();
        #pragma unroll
        for (int mt = 0; mt < 2; mt++) {
            const uint32_t ab = wbase + (uint32_t)(mt * 16 * WROW) * 2 + a_lane;
            #pragma unroll
            for (int ks = 0; ks < 8; ks++) {
                unsigned ah0, ah1, ah2, ah3;
                ldsm4(ah0, ah1, ah2, ah3, ab + ks * 32);
                #pragma unroll
                for (int nt = 0; nt < 4; nt++) {
                    const uint4 bb = breg[ks][nt];
                    mma_bf16(c[mt][nt], ah0, ah1, ah2, ah3, bb.x, bb.y);
                }
            }
        }

        // ---- pass 2: hi x Bl + lo x Bh ----
        CP_WAIT(0);
        __syncwarp();
        #pragma unroll
        for (int mt = 0; mt < 2; mt++) {
            const uint32_t ab = wbase + (uint32_t)(mt * 16 * WROW) * 2 + a_lane;
            #pragma unroll
            for (int ks = 0; ks < 8; ks++) {
                unsigned ah0, ah1, ah2, ah3, al0, al1, al2, al3;
                ldsm4(ah0, ah1, ah2, ah3, ab + ks * 32);
                ldsm4(al0, al1, al2, al3, ab + (uint32_t)WHALF * 2 + ks * 32);
                #pragma unroll
                for (int nt = 0; nt < 4; nt++) {
                    const uint4 bb = breg[ks][nt];
                    mma_bf16(c[mt][nt], ah0, ah1, ah2, ah3, bb.z, bb.w);
                    mma_bf16(c[mt][nt], al0, al1, al2, al3, bb.x, bb.y);
                }
            }
        }

        // ---- partials [w][row][36] ----
        #pragma unroll
        for (int mt = 0; mt < 2; mt++) {
            #pragma unroll
            for (int nt = 0; nt < 4; nt++) {
                const int row = mt * 16 + g;
                const int cc = nt * 8 + 2 * t4;
                float* p0 = &s_p[(wid * 32 + row) * 36 + cc];
                p0[0] = c[mt][nt][0]; p0[1] = c[mt][nt][1];
                float* p1 = &s_p[(wid * 32 + row + 8) * 36 + cc];
                p1[0] = c[mt][nt][2]; p1[1] = c[mt][nt][3];
            }
        }
        __syncthreads();

        // ---- reduce 8 warps + epilogue ----
        float4 s = {0.f, 0.f, 0.f, 0.f};
        #pragma unroll
        for (int w = 0; w < 8; w++) {
            const float4 p = *reinterpret_cast<const float4*>(&s_p[(w * 32 + er) * 36 + ec]);
            s.x += p.x; s.y += p.y; s.z += p.z; s.w += p.w;
        }
        const float v0 = tanhf(s.x + xv.x);
        const float v1 = tanhf(s.y + xv.y);
        const float v2 = tanhf(s.z + xv.z);
        const float v3 = tanhf(s.w + xv.w);

        {
            unsigned short h0s, l0s, h1s, l1s, h2s, l2s, h3s, l3s;
            split2(v0, h0s, l0s); split2(v1, h1s, l1s);
            split2(v2, h2s, l2s); split2(v3, h3s, l3s);
            const size_t hoff = (size_t)(m0 + er) * DIM + n0 + ec;
            uint2 hh = { pck(h0s, h1s), pck(h2s, h3s) };
            uint2 hl = { pck(l0s, l1s), pck(l2s, l3s) };
            *reinterpret_cast<uint2*>(&g_hh[wb][hoff]) = hh;
            *reinterpret_cast<uint2*>(&g_hl[wb][hoff]) = hl;
        }
        __syncthreads();
        if (tid == 0) st_rel(&g_flag[mblk][nstrip * 32], (unsigned)(t + 2));

        const float4 ov = { v0, v1, v2, v3 };
        *reinterpret_cast<float4*>(&out[obase]) = ov;
    }
}

// ---------------------------------------------------------------------------
// Launcher: inputs: x, h0, Wx, Wh, b
// ---------------------------------------------------------------------------
extern "C" void kernel_launch(void* const* d_in, const int* in_sizes, int n_in,
                              void* d_out, int out_size)
{
    const float* x  = (const float*)d_in[0];
    const float* h0 = (const float*)d_in[1];
    const float* Wx = (const float*)d_in[2];
    const float* Wh = (const float*)d_in[3];
    const float* b  = (const float*)d_in[4];
    float* out = (float*)d_out;

    cudaFuncSetAttribute(rnn_rec_kernel,
                         cudaFuncAttributeMaxDynamicSharedMemorySize, DYN_R);
    cudaFuncSetAttribute(gemm_xp_mma,
                         cudaFuncAttributeMaxDynamicSharedMemorySize, 2 * STG_BYTES);

    void* f0 = nullptr;
    cudaGetSymbolAddress(&f0, g_flag);
    cudaMemsetAsync(f0, 0, sizeof(unsigned) * 4 * 32 * 32);

    split_x_kernel<<<2048, 256>>>(x);
    {
        dim3 grid(DIM / 32, DIM / 32);
        split_wt_kernel<<<grid, 256>>>(Wx);
    }
    {
        dim3 grid(DIM / 64, (SEQ * BATCH) / 64);
        gemm_xp_mma<<<grid, 256, 2 * STG_BYTES>>>(b);
    }
    rnn_rec_kernel<<<GRID_R, THREADS_R, DYN_R>>>(h0, Wh, out);
}